// round 2
// baseline (speedup 1.0000x reference)
#include <cuda_runtime.h>
#include <math.h>

#define TT 4096
#define NB 8
#define NBT (NB*TT)

__device__ __align__(256) float g_s1[NB*208*TT];
__device__ __align__(256) float g_s2[NB*160*TT];
__device__ __align__(256) float g_x [NBT*64];
__device__ __align__(256) float g_q [NBT*64];
__device__ __align__(256) float g_k [NBT*64];
__device__ __align__(256) float g_v [NBT*64];

// ============ stage 1: causal conv (1x3) + maxpool3(freq) + relu ============
// one thread per (b, f2, t), computes all 8 output channels
__global__ void k_s1(const float* __restrict__ spec, const float* __restrict__ w,
                     const float* __restrict__ bias){
    int id = blockIdx.x*256 + threadIdx.x;
    int t  = id & (TT-1);
    int r  = id >> 12;
    int f2 = r % 26, b = r / 26;
    const float* sp = spec + (size_t)(b*81 + f2*3)*TT + t;
    float s[5][3];
    #pragma unroll
    for (int j=0;j<5;j++)
        #pragma unroll
        for (int i=0;i<3;i++)
            s[j][i] = (t+i < TT) ? sp[j*TT+i] : 0.f;
    #pragma unroll
    for (int c=0;c<8;c++){
        float a0=0.f,a1=0.f,a2=0.f;
        #pragma unroll
        for (int i=0;i<3;i++){
            if (t+i < TT){
                float w0=__ldg(w+(i*8+c)*3+0), w1=__ldg(w+(i*8+c)*3+1), w2=__ldg(w+(i*8+c)*3+2);
                float bb=__ldg(bias+i*8+c);
                a0 += bb + w0*s[0][i]+w1*s[1][i]+w2*s[2][i];
                a1 += bb + w0*s[1][i]+w1*s[2][i]+w2*s[3][i];
                a2 += bb + w0*s[2][i]+w1*s[3][i]+w2*s[4][i];
            }
        }
        float m = fmaxf(fmaxf(a0,a1),a2);
        g_s1[((size_t)(b*8+c)*26+f2)*TT + t] = fmaxf(m, 0.f);
    }
}

// ============ stage 2: conv (1x12) + maxpool3 + relu ============
__global__ void k_s2(const float* __restrict__ w2, const float* __restrict__ b2){
    extern __shared__ float sm[];
    float* s1s = sm;            // [208][64]
    float* ws  = sm + 208*64;   // 3072
    int tid = threadIdx.x, b = blockIdx.y, t0 = blockIdx.x*64;
    for (int i=tid; i<208*64; i+=256){
        int tl = i & 63, fr = i >> 6;
        s1s[i] = g_s1[((size_t)(b*208+fr))*TT + t0 + tl];
    }
    for (int i=tid; i<3072; i+=256) ws[i] = w2[i];
    __syncthreads();
    int tl = tid & 63, g = tid >> 6;
    for (int cb=0; cb<2; cb++){
        int co0 = g*8 + cb*4;
        float acc[4][5][3];
        #pragma unroll
        for (int u=0;u<4;u++){
            float bb = __ldg(b2 + co0 + u);
            #pragma unroll
            for (int f2=0;f2<5;f2++){ acc[u][f2][0]=bb; acc[u][f2][1]=bb; acc[u][f2][2]=bb; }
        }
        for (int cin=0; cin<8; cin++){
            float sv[26];
            #pragma unroll
            for (int ff=0; ff<26; ff++) sv[ff] = s1s[(cin*26+ff)*64 + tl];
            float w[4][12];
            #pragma unroll
            for (int u=0;u<4;u++)
                #pragma unroll
                for (int k=0;k<12;k++) w[u][k] = ws[(co0+u)*96 + cin*12 + k];
            #pragma unroll
            for (int f2=0; f2<5; f2++)
                #pragma unroll
                for (int k=0;k<12;k++)
                    #pragma unroll
                    for (int u=0;u<4;u++){
                        float wk = w[u][k];
                        acc[u][f2][0] += wk*sv[f2*3+k+0];
                        acc[u][f2][1] += wk*sv[f2*3+k+1];
                        acc[u][f2][2] += wk*sv[f2*3+k+2];
                    }
        }
        #pragma unroll
        for (int u=0;u<4;u++)
            #pragma unroll
            for (int f2=0;f2<5;f2++){
                float m = fmaxf(fmaxf(acc[u][f2][0],acc[u][f2][1]),acc[u][f2][2]);
                g_s2[((size_t)((b*32+co0+u)*5+f2))*TT + t0 + tl] = fmaxf(m, 0.f);
            }
    }
}

// ============ stage 3: causal conv (1x3, cin32,co64) + maxpool3 + relu ============
__global__ void __launch_bounds__(512) k_s3(const float* __restrict__ w3, const float* __restrict__ b3){
    extern __shared__ float sm[];
    float* s2s = sm;              // [160][132] pitch 132
    float* w3s = sm + 160*132;    // 18432
    int tid = threadIdx.x, b = blockIdx.y, t0 = blockIdx.x*128;
    for (int i=tid; i<160*132; i+=512){
        int tl = i % 132, fr = i / 132;
        int tg = t0 + tl;
        s2s[i] = (tg < TT && tl < 130) ? g_s2[((size_t)(b*160+fr))*TT + tg] : 0.f;
    }
    for (int i=tid; i<18432; i+=512){
        int co = i & 63, r = i >> 6;
        int k = r % 3; r /= 3;
        int cin = r & 31, ii = r >> 5;
        w3s[i] = w3[((size_t)(ii*64+co)*32+cin)*3 + k];
    }
    __syncthreads();
    int co = tid & 63, tg8 = tid >> 6;
    float bb0 = __ldg(b3+co), bb1 = __ldg(b3+64+co), bb2 = __ldg(b3+128+co);
    for (int chunk=0; chunk<2; chunk++){
        int tlbase = tg8*16 + chunk*8;
        float acc[8][3];
        #pragma unroll
        for (int rr=0;rr<8;rr++){ acc[rr][0]=0.f; acc[rr][1]=0.f; acc[rr][2]=0.f; }
        for (int cin=0; cin<32; cin++){
            float sv[5][12];
            #pragma unroll
            for (int ff=0; ff<5; ff++){
                const float4* p = (const float4*)(s2s + (cin*5+ff)*132 + tlbase);
                float4 u0=p[0], u1=p[1], u2=p[2];
                sv[ff][0]=u0.x; sv[ff][1]=u0.y; sv[ff][2]=u0.z; sv[ff][3]=u0.w;
                sv[ff][4]=u1.x; sv[ff][5]=u1.y; sv[ff][6]=u1.z; sv[ff][7]=u1.w;
                sv[ff][8]=u2.x; sv[ff][9]=u2.y; sv[ff][10]=u2.z; sv[ff][11]=u2.w;
            }
            #pragma unroll
            for (int ii=0; ii<3; ii++)
                #pragma unroll
                for (int k=0; k<3; k++){
                    float wk = w3s[((ii*32+cin)*3+k)*64 + co];
                    #pragma unroll
                    for (int f=0; f<3; f++)
                        #pragma unroll
                        for (int rr=0; rr<8; rr++)
                            acc[rr][f] += wk*sv[f+k][rr+ii];
                }
        }
        #pragma unroll
        for (int rr=0; rr<8; rr++){
            int tg = t0 + tlbase + rr;
            float a0=acc[rr][0]+bb0, a1=acc[rr][1]+bb0, a2=acc[rr][2]+bb0;
            if (tg+1 < TT){ a0+=bb1; a1+=bb1; a2+=bb1; }
            if (tg+2 < TT){ a0+=bb2; a1+=bb2; a2+=bb2; }
            float m = fmaxf(fmaxf(a0,a1),a2);
            g_x[((size_t)(b*TT+tg))*64 + co] = fmaxf(m, 0.f);
        }
    }
}

// ============ LN1 + QKV projection ============
__global__ void k_qkv(const float* __restrict__ Wq, const float* __restrict__ bq,
                      const float* __restrict__ Wk, const float* __restrict__ bk,
                      const float* __restrict__ Wv, const float* __restrict__ bv,
                      const float* __restrict__ gam, const float* __restrict__ bet){
    extern __shared__ float sm[];
    float* Ws = sm;               // [64][193]
    float* bs = sm + 64*193;      // 192
    float* hs = bs + 192;         // [32][65]
    int tid = threadIdx.x;
    for (int i=tid; i<4096; i+=256){
        int col = i >> 6, d = i & 63;
        Ws[d*193 + col]       = Wq[i];
        Ws[d*193 + 64 + col]  = Wk[i];
        Ws[d*193 + 128 + col] = Wv[i];
    }
    if (tid < 64){ bs[tid]=bq[tid]; bs[64+tid]=bk[tid]; bs[128+tid]=bv[tid]; }
    int tok = tid >> 3, lane = tid & 7;
    int gtok = blockIdx.x*32 + tok;
    const float* xr = g_x + (size_t)gtok*64 + lane*8;
    float4 u0 = *(const float4*)xr, u1 = *(const float4*)(xr+4);
    float v[8] = {u0.x,u0.y,u0.z,u0.w,u1.x,u1.y,u1.z,u1.w};
    float s=0.f, ss=0.f;
    #pragma unroll
    for (int m=0;m<8;m++){ s += v[m]; ss += v[m]*v[m]; }
    #pragma unroll
    for (int o=1;o<8;o<<=1){ s += __shfl_xor_sync(0xffffffffu,s,o); ss += __shfl_xor_sync(0xffffffffu,ss,o); }
    float mean = s*(1.f/64.f);
    float var  = ss*(1.f/64.f) - mean*mean;
    float rstd = rsqrtf(fmaxf(var,0.f) + 1e-5f);
    #pragma unroll
    for (int m=0;m<8;m++){
        int dd = lane*8+m;
        hs[tok*65+dd] = (v[m]-mean)*rstd*__ldg(gam+dd) + __ldg(bet+dd);
    }
    __syncthreads();
    int x32 = tid & 31, y8 = tid >> 5;
    float acc[4][6];
    #pragma unroll
    for (int a=0;a<4;a++)
        #pragma unroll
        for (int c=0;c<6;c++) acc[a][c]=0.f;
    #pragma unroll 8
    for (int d=0; d<64; d++){
        float hv[4];
        #pragma unroll
        for (int t4=0;t4<4;t4++) hv[t4] = hs[(y8*4+t4)*65 + d];
        float wv[6];
        #pragma unroll
        for (int cc=0;cc<6;cc++) wv[cc] = Ws[d*193 + x32 + 32*cc];
        #pragma unroll
        for (int t4=0;t4<4;t4++)
            #pragma unroll
            for (int cc=0;cc<6;cc++) acc[t4][cc] += hv[t4]*wv[cc];
    }
    int gt0 = blockIdx.x*32 + y8*4;
    #pragma unroll
    for (int t4=0;t4<4;t4++)
        #pragma unroll
        for (int cc=0;cc<6;cc++){
            int col = x32 + 32*cc;
            float val = acc[t4][cc] + bs[col];
            float* dst = (col < 64) ? g_q : (col < 128) ? g_k : g_v;
            dst[((size_t)(gt0+t4))*64 + (col & 63)] = val;
        }
}

// ============ dilated local attention (6 keys) + residual ============
__global__ void k_attn(const float* __restrict__ Er, int shift){
    int id = blockIdx.x*256 + threadIdx.x;
    int t = id & (TT-1);
    int r = id >> 12;
    int h = r & 7, b = r >> 3;
    size_t bt = (size_t)b*TT + t;
    const float* qp = g_q + bt*64 + h*8;
    float4 q0 = *(const float4*)qp, q1 = *(const float4*)(qp+4);
    float q[8] = {q0.x,q0.y,q0.z,q0.w,q1.x,q1.y,q1.z,q1.w};
    const float* er = Er + h*48;
    float lg[6];
    #pragma unroll
    for (int j=0;j<6;j++){
        float qe = 0.f;
        #pragma unroll
        for (int d=0;d<8;d++) qe += q[d]*__ldg(er + d*6 + j);
        lg[j] = qe;
    }
    int sh[6]; sh[0]=0; sh[1]=0; sh[2]=shift; sh[3]=2*shift; sh[4]=3*shift; sh[5]=4*shift;
    #pragma unroll
    for (int j=0;j<6;j++){
        int tp = t - sh[j];
        float qk = 0.f;
        if (tp >= 0){
            const float* kp = g_k + ((size_t)b*TT+tp)*64 + h*8;
            float4 k0 = *(const float4*)kp, k1 = *(const float4*)(kp+4);
            qk = q[0]*k0.x + q[1]*k0.y + q[2]*k0.z + q[3]*k0.w
               + q[4]*k1.x + q[5]*k1.y + q[6]*k1.z + q[7]*k1.w;
        }
        lg[j] = (qk + lg[j]) * 0.3535533905932738f;
    }
    float mx = lg[0];
    #pragma unroll
    for (int j=1;j<6;j++) mx = fmaxf(mx, lg[j]);
    float e[6], se = 0.f;
    #pragma unroll
    for (int j=0;j<6;j++){ e[j] = expf(lg[j]-mx); se += e[j]; }
    float inv = 1.f/se;
    float o[8] = {0,0,0,0,0,0,0,0};
    #pragma unroll
    for (int j=0;j<6;j++){
        int tp = t - sh[j];
        if (tp >= 0){
            const float* vp = g_v + ((size_t)b*TT+tp)*64 + h*8;
            float4 v0 = *(const float4*)vp, v1 = *(const float4*)(vp+4);
            float a = e[j];
            o[0]+=a*v0.x; o[1]+=a*v0.y; o[2]+=a*v0.z; o[3]+=a*v0.w;
            o[4]+=a*v1.x; o[5]+=a*v1.y; o[6]+=a*v1.z; o[7]+=a*v1.w;
        }
    }
    float* xp = g_x + bt*64 + h*8;
    float4 x0 = *(float4*)xp, x1 = *(float4*)(xp+4);
    x0.x+=o[0]*inv; x0.y+=o[1]*inv; x0.z+=o[2]*inv; x0.w+=o[3]*inv;
    x1.x+=o[4]*inv; x1.y+=o[5]*inv; x1.z+=o[6]*inv; x1.w+=o[7]*inv;
    *(float4*)xp = x0; *(float4*)(xp+4) = x1;
}

// ============ LN2 + FF (exact gelu) + residual ============
__global__ void k_ff(const float* __restrict__ W1p, const float* __restrict__ b1p,
                     const float* __restrict__ W2p, const float* __restrict__ b2p,
                     const float* __restrict__ gam, const float* __restrict__ bet){
    __shared__ float sm[10528];
    float* W1s = sm;            // [64][65]
    float* W2s = sm + 4160;
    float* bs  = sm + 8320;     // 128
    float* hs  = sm + 8448;     // [32][65]
    int tid = threadIdx.x;
    for (int i=tid; i<4096; i+=256){
        int col = i >> 6, d = i & 63;
        W1s[d*65+col] = W1p[i];
        W2s[d*65+col] = W2p[i];
    }
    if (tid < 64){ bs[tid]=b1p[tid]; bs[64+tid]=b2p[tid]; }
    int tok = tid >> 3, lane = tid & 7;
    int gtok = blockIdx.x*32 + tok;
    const float* xr = g_x + (size_t)gtok*64 + lane*8;
    float4 u0 = *(const float4*)xr, u1 = *(const float4*)(xr+4);
    float v[8] = {u0.x,u0.y,u0.z,u0.w,u1.x,u1.y,u1.z,u1.w};
    float s=0.f, ss=0.f;
    #pragma unroll
    for (int m=0;m<8;m++){ s += v[m]; ss += v[m]*v[m]; }
    #pragma unroll
    for (int o=1;o<8;o<<=1){ s += __shfl_xor_sync(0xffffffffu,s,o); ss += __shfl_xor_sync(0xffffffffu,ss,o); }
    float mean = s*(1.f/64.f);
    float var  = ss*(1.f/64.f) - mean*mean;
    float rstd = rsqrtf(fmaxf(var,0.f) + 1e-5f);
    #pragma unroll
    for (int m=0;m<8;m++){
        int dd = lane*8+m;
        hs[tok*65+dd] = (v[m]-mean)*rstd*__ldg(gam+dd) + __ldg(bet+dd);
    }
    __syncthreads();
    int c2 = tid & 31, r4 = tid >> 5;
    float acc[4][2] = {{0,0},{0,0},{0,0},{0,0}};
    #pragma unroll 8
    for (int d=0; d<64; d++){
        float w0 = W1s[d*65 + c2], w1 = W1s[d*65 + c2 + 32];
        #pragma unroll
        for (int t4=0;t4<4;t4++){
            float hv = hs[(r4*4+t4)*65 + d];
            acc[t4][0] += hv*w0; acc[t4][1] += hv*w1;
        }
    }
    __syncthreads();
    #pragma unroll
    for (int t4=0;t4<4;t4++)
        #pragma unroll
        for (int cc=0;cc<2;cc++){
            float z = acc[t4][cc] + bs[c2 + 32*cc];
            hs[(r4*4+t4)*65 + c2 + 32*cc] = 0.5f*z*(1.f + erff(z*0.7071067811865475f));
        }
    __syncthreads();
    float acc2[4][2] = {{0,0},{0,0},{0,0},{0,0}};
    #pragma unroll 8
    for (int d=0; d<64; d++){
        float w0 = W2s[d*65 + c2], w1 = W2s[d*65 + c2 + 32];
        #pragma unroll
        for (int t4=0;t4<4;t4++){
            float hv = hs[(r4*4+t4)*65 + d];
            acc2[t4][0] += hv*w0; acc2[t4][1] += hv*w1;
        }
    }
    #pragma unroll
    for (int t4=0;t4<4;t4++)
        #pragma unroll
        for (int cc=0;cc<2;cc++){
            int col = c2 + 32*cc;
            int gt = blockIdx.x*32 + r4*4 + t4;
            g_x[((size_t)gt)*64 + col] += acc2[t4][cc] + bs[64+col];
        }
}

// ============ 1x1 conv out + sigmoid ============
__global__ void k_out(const float* __restrict__ ow, const float* __restrict__ ob,
                      float* __restrict__ out){
    int id = blockIdx.x*256 + threadIdx.x;   // b*T + t
    int t = id & (TT-1), b = id >> 12;
    const float4* xp = (const float4*)(g_x + (size_t)id*64);
    float a0 = __ldg(ob), a1 = __ldg(ob+1);
    #pragma unroll
    for (int d4=0; d4<16; d4++){
        float4 xv = xp[d4];
        a0 += xv.x*__ldg(ow+d4*4) + xv.y*__ldg(ow+d4*4+1) + xv.z*__ldg(ow+d4*4+2) + xv.w*__ldg(ow+d4*4+3);
        a1 += xv.x*__ldg(ow+64+d4*4) + xv.y*__ldg(ow+64+d4*4+1) + xv.z*__ldg(ow+64+d4*4+2) + xv.w*__ldg(ow+64+d4*4+3);
    }
    out[((size_t)(b*2))*TT + t]   = 1.f/(1.f+expf(-a0));
    out[((size_t)(b*2+1))*TT + t] = 1.f/(1.f+expf(-a1));
}

extern "C" void kernel_launch(void* const* d_in, const int* in_sizes, int n_in,
                              void* d_out, int out_size){
    const float* spec = (const float*)d_in[0];
    const float* c1w = (const float*)d_in[1];
    const float* c1b = (const float*)d_in[2];
    const float* c2w = (const float*)d_in[3];
    const float* c2b = (const float*)d_in[4];
    const float* c3w = (const float*)d_in[5];
    const float* c3b = (const float*)d_in[6];
    const float* Wq  = (const float*)d_in[7];
    const float* bq  = (const float*)d_in[8];
    const float* Wk  = (const float*)d_in[9];
    const float* bk  = (const float*)d_in[10];
    const float* Wv  = (const float*)d_in[11];
    const float* bv  = (const float*)d_in[12];
    const float* Er  = (const float*)d_in[13];
    const float* g1  = (const float*)d_in[14];
    const float* be1 = (const float*)d_in[15];
    const float* W1  = (const float*)d_in[16];
    const float* b1  = (const float*)d_in[17];
    const float* W2  = (const float*)d_in[18];
    const float* b2  = (const float*)d_in[19];
    const float* g2  = (const float*)d_in[20];
    const float* be2 = (const float*)d_in[21];
    const float* ow  = (const float*)d_in[22];
    const float* ob  = (const float*)d_in[23];

    cudaFuncSetAttribute(k_s2,  cudaFuncAttributeMaxDynamicSharedMemorySize, 65536);
    cudaFuncSetAttribute(k_s3,  cudaFuncAttributeMaxDynamicSharedMemorySize, 158208);
    cudaFuncSetAttribute(k_qkv, cudaFuncAttributeMaxDynamicSharedMemorySize, 58496);

    k_s1<<<3328, 256>>>(spec, c1w, c1b);
    k_s2<<<dim3(64,8), 256, 65536>>>(c2w, c2b);
    k_s3<<<dim3(32,8), 512, 158208>>>(c3w, c3b);
    for (int L=0; L<11; L++){
        k_qkv<<<1024, 256, 58496>>>(Wq+L*4096, bq+L*64, Wk+L*4096, bk+L*64,
                                    Wv+L*4096, bv+L*64, g1+L*64, be1+L*64);
        k_attn<<<1024, 256>>>(Er+L*384, 1<<L);
        k_ff<<<1024, 256>>>(W1+L*4096, b1+L*64, W2+L*4096, b2+L*64, g2+L*64, be2+L*64);
    }
    k_out<<<128, 256>>>(ow, ob, (float*)d_out);
}

// round 5
// speedup vs baseline: 1.0850x; 1.0850x over previous
#include <cuda_runtime.h>
#include <math.h>

#define TT 4096
#define NB 8
#define NBT (NB*TT)

__device__ __align__(256) float g_s1[NB*208*TT];
__device__ __align__(256) float g_s2[NB*160*TT];
__device__ __align__(256) float g_x [NBT*64];
__device__ __align__(256) float g_q [NBT*64];
__device__ __align__(256) float g_k [NBT*64];
__device__ __align__(256) float g_v [NBT*64];

// ============ stage 1: causal conv (1x3) + maxpool3(freq) + relu ============
__global__ void k_s1(const float* __restrict__ spec, const float* __restrict__ w,
                     const float* __restrict__ bias){
    int id = blockIdx.x*256 + threadIdx.x;
    int t  = id & (TT-1);
    int r  = id >> 12;
    int f2 = r % 26, b = r / 26;
    const float* sp = spec + (size_t)(b*81 + f2*3)*TT + t;
    float s[5][3];
    #pragma unroll
    for (int j=0;j<5;j++)
        #pragma unroll
        for (int i=0;i<3;i++)
            s[j][i] = (t+i < TT) ? sp[j*TT+i] : 0.f;
    #pragma unroll
    for (int c=0;c<8;c++){
        float a0=0.f,a1=0.f,a2=0.f;
        #pragma unroll
        for (int i=0;i<3;i++){
            if (t+i < TT){
                float w0=__ldg(w+(i*8+c)*3+0), w1=__ldg(w+(i*8+c)*3+1), w2=__ldg(w+(i*8+c)*3+2);
                float bb=__ldg(bias+i*8+c);
                a0 += bb + w0*s[0][i]+w1*s[1][i]+w2*s[2][i];
                a1 += bb + w0*s[1][i]+w1*s[2][i]+w2*s[3][i];
                a2 += bb + w0*s[2][i]+w1*s[3][i]+w2*s[4][i];
            }
        }
        float m = fmaxf(fmaxf(a0,a1),a2);
        g_s1[((size_t)(b*8+c)*26+f2)*TT + t] = fmaxf(m, 0.f);
    }
}

// ============ stage 2: conv (1x12) + maxpool3 + relu ============
__global__ void k_s2(const float* __restrict__ w2, const float* __restrict__ b2){
    extern __shared__ float sm[];
    float* s1s = sm;            // [208][64]
    float* ws  = sm + 208*64;   // 3072
    int tid = threadIdx.x, b = blockIdx.y, t0 = blockIdx.x*64;
    for (int i=tid; i<208*64; i+=256){
        int tl = i & 63, fr = i >> 6;
        s1s[i] = g_s1[((size_t)(b*208+fr))*TT + t0 + tl];
    }
    for (int i=tid; i<3072; i+=256) ws[i] = w2[i];
    __syncthreads();
    int tl = tid & 63, g = tid >> 6;
    for (int cb=0; cb<2; cb++){
        int co0 = g*8 + cb*4;
        float acc[4][5][3];
        #pragma unroll
        for (int u=0;u<4;u++){
            float bb = __ldg(b2 + co0 + u);
            #pragma unroll
            for (int f2=0;f2<5;f2++){ acc[u][f2][0]=bb; acc[u][f2][1]=bb; acc[u][f2][2]=bb; }
        }
        for (int cin=0; cin<8; cin++){
            float sv[26];
            #pragma unroll
            for (int ff=0; ff<26; ff++) sv[ff] = s1s[(cin*26+ff)*64 + tl];
            float w[4][12];
            #pragma unroll
            for (int u=0;u<4;u++)
                #pragma unroll
                for (int k=0;k<12;k++) w[u][k] = ws[(co0+u)*96 + cin*12 + k];
            #pragma unroll
            for (int f2=0; f2<5; f2++)
                #pragma unroll
                for (int k=0;k<12;k++)
                    #pragma unroll
                    for (int u=0;u<4;u++){
                        float wk = w[u][k];
                        acc[u][f2][0] += wk*sv[f2*3+k+0];
                        acc[u][f2][1] += wk*sv[f2*3+k+1];
                        acc[u][f2][2] += wk*sv[f2*3+k+2];
                    }
        }
        #pragma unroll
        for (int u=0;u<4;u++)
            #pragma unroll
            for (int f2=0;f2<5;f2++){
                float m = fmaxf(fmaxf(acc[u][f2][0],acc[u][f2][1]),acc[u][f2][2]);
                g_s2[((size_t)((b*32+co0+u)*5+f2))*TT + t0 + tl] = fmaxf(m, 0.f);
            }
    }
}

// ============ stage 3: causal conv (1x3, cin32,co64) + maxpool3 + relu ============
__global__ void __launch_bounds__(512) k_s3(const float* __restrict__ w3, const float* __restrict__ b3){
    extern __shared__ float sm[];
    float* s2s = sm;              // [160][132]
    float* w3s = sm + 160*132;    // 18432
    int tid = threadIdx.x, b = blockIdx.y, t0 = blockIdx.x*128;
    for (int i=tid; i<160*132; i+=512){
        int tl = i % 132, fr = i / 132;
        int tg = t0 + tl;
        s2s[i] = (tg < TT && tl < 130) ? g_s2[((size_t)(b*160+fr))*TT + tg] : 0.f;
    }
    for (int i=tid; i<18432; i+=512){
        int co = i & 63, r = i >> 6;
        int k = r % 3; r /= 3;
        int cin = r & 31, ii = r >> 5;
        w3s[i] = w3[((size_t)(ii*64+co)*32+cin)*3 + k];
    }
    __syncthreads();
    int co = tid & 63, tg8 = tid >> 6;
    float bb0 = __ldg(b3+co), bb1 = __ldg(b3+64+co), bb2 = __ldg(b3+128+co);
    for (int chunk=0; chunk<2; chunk++){
        int tlbase = tg8*16 + chunk*8;
        float acc[8][3];
        #pragma unroll
        for (int rr=0;rr<8;rr++){ acc[rr][0]=0.f; acc[rr][1]=0.f; acc[rr][2]=0.f; }
        for (int cin=0; cin<32; cin++){
            float sv[5][12];
            #pragma unroll
            for (int ff=0; ff<5; ff++){
                const float4* p = (const float4*)(s2s + (cin*5+ff)*132 + tlbase);
                float4 u0=p[0], u1=p[1], u2=p[2];
                sv[ff][0]=u0.x; sv[ff][1]=u0.y; sv[ff][2]=u0.z; sv[ff][3]=u0.w;
                sv[ff][4]=u1.x; sv[ff][5]=u1.y; sv[ff][6]=u1.z; sv[ff][7]=u1.w;
                sv[ff][8]=u2.x; sv[ff][9]=u2.y; sv[ff][10]=u2.z; sv[ff][11]=u2.w;
            }
            #pragma unroll
            for (int ii=0; ii<3; ii++)
                #pragma unroll
                for (int k=0; k<3; k++){
                    float wk = w3s[((ii*32+cin)*3+k)*64 + co];
                    #pragma unroll
                    for (int f=0; f<3; f++)
                        #pragma unroll
                        for (int rr=0; rr<8; rr++)
                            acc[rr][f] += wk*sv[f+k][rr+ii];
                }
        }
        #pragma unroll
        for (int rr=0; rr<8; rr++){
            int tg = t0 + tlbase + rr;
            float a0=acc[rr][0]+bb0, a1=acc[rr][1]+bb0, a2=acc[rr][2]+bb0;
            if (tg+1 < TT){ a0+=bb1; a1+=bb1; a2+=bb1; }
            if (tg+2 < TT){ a0+=bb2; a1+=bb2; a2+=bb2; }
            float m = fmaxf(fmaxf(a0,a1),a2);
            g_x[((size_t)(b*TT+tg))*64 + co] = fmaxf(m, 0.f);
        }
    }
}

// ============ LN1 + QKV projection (128 tokens/block, 8x6 reg tiles) ============
__global__ void __launch_bounds__(512) k_qkv(
        const float* __restrict__ Wq, const float* __restrict__ bq,
        const float* __restrict__ Wk, const float* __restrict__ bk,
        const float* __restrict__ Wv, const float* __restrict__ bv,
        const float* __restrict__ gam, const float* __restrict__ bet){
    extern __shared__ float sm[];
    float* Ws = sm;               // [64][193]
    float* bs = sm + 64*193;      // 192
    float* hs = bs + 192;         // [128][68]
    int tid = threadIdx.x;
    for (int i=tid; i<4096; i+=512){
        int col = i >> 6, d = i & 63;
        Ws[d*193 + col]       = Wq[i];
        Ws[d*193 + 64 + col]  = Wk[i];
        Ws[d*193 + 128 + col] = Wv[i];
    }
    if (tid < 64){ bs[tid]=bq[tid]; bs[64+tid]=bk[tid]; bs[128+tid]=bv[tid]; }
    int tok = tid >> 2, lane = tid & 3;
    int gtok = blockIdx.x*128 + tok;
    const float* xr = g_x + (size_t)gtok*64 + lane*16;
    float v[16];
    #pragma unroll
    for (int c=0;c<4;c++){
        float4 u = *(const float4*)(xr + c*4);
        v[c*4]=u.x; v[c*4+1]=u.y; v[c*4+2]=u.z; v[c*4+3]=u.w;
    }
    float s=0.f, ss=0.f;
    #pragma unroll
    for (int m=0;m<16;m++){ s += v[m]; ss += v[m]*v[m]; }
    s += __shfl_xor_sync(0xffffffffu,s,1); ss += __shfl_xor_sync(0xffffffffu,ss,1);
    s += __shfl_xor_sync(0xffffffffu,s,2); ss += __shfl_xor_sync(0xffffffffu,ss,2);
    float mean = s*(1.f/64.f);
    float var  = ss*(1.f/64.f) - mean*mean;
    float rstd = rsqrtf(fmaxf(var,0.f) + 1e-5f);
    #pragma unroll
    for (int m=0;m<16;m++){
        int dd = lane*16+m;
        hs[tok*68+dd] = (v[m]-mean)*rstd*__ldg(gam+dd) + __ldg(bet+dd);
    }
    __syncthreads();
    int x32 = tid & 31, rg = tid >> 5;
    float acc[8][6];
    #pragma unroll
    for (int r=0;r<8;r++)
        #pragma unroll
        for (int c=0;c<6;c++) acc[r][c]=0.f;
    #pragma unroll 4
    for (int d=0; d<64; d+=4){
        float hv[8][4];
        #pragma unroll
        for (int r=0;r<8;r++){
            float4 u = *(const float4*)(hs + (rg*8+r)*68 + d);
            hv[r][0]=u.x; hv[r][1]=u.y; hv[r][2]=u.z; hv[r][3]=u.w;
        }
        #pragma unroll
        for (int dd=0; dd<4; dd++){
            float wv[6];
            #pragma unroll
            for (int cc=0;cc<6;cc++) wv[cc] = Ws[(d+dd)*193 + x32 + 32*cc];
            #pragma unroll
            for (int r=0;r<8;r++)
                #pragma unroll
                for (int cc=0;cc<6;cc++) acc[r][cc] += hv[r][dd]*wv[cc];
        }
    }
    int gt0 = blockIdx.x*128 + rg*8;
    #pragma unroll
    for (int r=0;r<8;r++)
        #pragma unroll
        for (int cc=0;cc<6;cc++){
            int col = x32 + 32*cc;
            float val = acc[r][cc] + bs[col];
            float* dst = (cc < 2) ? g_q : (cc < 4) ? g_k : g_v;
            dst[((size_t)(gt0+r))*64 + (col & 63)] = val;
        }
}

// ============ attention + residual + LN2 + FF + residual (fused) ============
__global__ void __launch_bounds__(256) k_attnff(
        const float* __restrict__ Er, int shift,
        const float* __restrict__ W1p, const float* __restrict__ b1p,
        const float* __restrict__ W2p, const float* __restrict__ b2p,
        const float* __restrict__ gam, const float* __restrict__ bet){
    extern __shared__ float sm[];
    float* W1s = sm;            // [64][65]
    float* W2s = sm + 4160;     // [64][65]
    float* bs  = sm + 8320;     // 128
    float* xs  = sm + 8448;     // [64][68]
    float* hs  = sm + 12800;    // [64][68]
    int tid = threadIdx.x;
    for (int i=tid; i<4096; i+=256){
        int col = i >> 6, d = i & 63;
        W1s[d*65+col] = W1p[i];
        W2s[d*65+col] = W2p[i];
    }
    if (tid < 64){ bs[tid]=b1p[tid]; bs[64+tid]=b2p[tid]; }

    {
        int tok = tid >> 2, hp = (tid & 3)*2;
        int gtok = blockIdx.x*64 + tok;
        int b = gtok >> 12, t = gtok & (TT-1);
        size_t bt = (size_t)b*TT + t;
        int sh[6]; sh[0]=0; sh[1]=0; sh[2]=shift; sh[3]=2*shift; sh[4]=3*shift; sh[5]=4*shift;
        #pragma unroll
        for (int hh=0; hh<2; hh++){
            int h = hp + hh;
            const float* qp = g_q + bt*64 + h*8;
            float4 q0 = *(const float4*)qp, q1 = *(const float4*)(qp+4);
            float q[8] = {q0.x,q0.y,q0.z,q0.w,q1.x,q1.y,q1.z,q1.w};
            const float* er = Er + h*48;
            float lg[6];
            #pragma unroll
            for (int j=0;j<6;j++){
                float qe = 0.f;
                #pragma unroll
                for (int d=0;d<8;d++) qe += q[d]*__ldg(er + d*6 + j);
                lg[j] = qe;
            }
            #pragma unroll
            for (int j=0;j<6;j++){
                int tp = t - sh[j];
                float qk = 0.f;
                if (tp >= 0){
                    const float* kp = g_k + ((size_t)b*TT+tp)*64 + h*8;
                    float4 k0 = *(const float4*)kp, k1 = *(const float4*)(kp+4);
                    qk = q[0]*k0.x + q[1]*k0.y + q[2]*k0.z + q[3]*k0.w
                       + q[4]*k1.x + q[5]*k1.y + q[6]*k1.z + q[7]*k1.w;
                }
                lg[j] = (qk + lg[j]) * 0.3535533905932738f;
            }
            float mx = lg[0];
            #pragma unroll
            for (int j=1;j<6;j++) mx = fmaxf(mx, lg[j]);
            float e[6], se = 0.f;
            #pragma unroll
            for (int j=0;j<6;j++){ e[j] = expf(lg[j]-mx); se += e[j]; }
            float inv = 1.f/se;
            float o[8] = {0,0,0,0,0,0,0,0};
            #pragma unroll
            for (int j=0;j<6;j++){
                int tp = t - sh[j];
                if (tp >= 0){
                    const float* vp = g_v + ((size_t)b*TT+tp)*64 + h*8;
                    float4 v0 = *(const float4*)vp, v1 = *(const float4*)(vp+4);
                    float a = e[j];
                    o[0]+=a*v0.x; o[1]+=a*v0.y; o[2]+=a*v0.z; o[3]+=a*v0.w;
                    o[4]+=a*v1.x; o[5]+=a*v1.y; o[6]+=a*v1.z; o[7]+=a*v1.w;
                }
            }
            const float* xp = g_x + (size_t)gtok*64 + h*8;
            float4 x0 = *(const float4*)xp, x1 = *(const float4*)(xp+4);
            float* xd = xs + tok*68 + h*8;
            xd[0]=x0.x+o[0]*inv; xd[1]=x0.y+o[1]*inv; xd[2]=x0.z+o[2]*inv; xd[3]=x0.w+o[3]*inv;
            xd[4]=x1.x+o[4]*inv; xd[5]=x1.y+o[5]*inv; xd[6]=x1.z+o[6]*inv; xd[7]=x1.w+o[7]*inv;
        }
    }
    __syncthreads();

    {
        int tok = tid >> 2, lane = tid & 3;
        float v[16];
        #pragma unroll
        for (int m=0;m<16;m++) v[m] = xs[tok*68 + lane*16 + m];
        float s=0.f, ss=0.f;
        #pragma unroll
        for (int m=0;m<16;m++){ s += v[m]; ss += v[m]*v[m]; }
        s += __shfl_xor_sync(0xffffffffu,s,1); ss += __shfl_xor_sync(0xffffffffu,ss,1);
        s += __shfl_xor_sync(0xffffffffu,s,2); ss += __shfl_xor_sync(0xffffffffu,ss,2);
        float mean = s*(1.f/64.f);
        float var  = ss*(1.f/64.f) - mean*mean;
        float rstd = rsqrtf(fmaxf(var,0.f) + 1e-5f);
        #pragma unroll
        for (int m=0;m<16;m++){
            int dd = lane*16+m;
            hs[tok*68+dd] = (v[m]-mean)*rstd*__ldg(gam+dd) + __ldg(bet+dd);
        }
    }
    __syncthreads();

    int c2 = tid & 31, rg = tid >> 5;
    float acc[8][2];
    #pragma unroll
    for (int r=0;r<8;r++){ acc[r][0]=0.f; acc[r][1]=0.f; }
    #pragma unroll 4
    for (int d=0; d<64; d+=4){
        float hv[8][4];
        #pragma unroll
        for (int r=0;r<8;r++){
            float4 u = *(const float4*)(hs + (rg*8+r)*68 + d);
            hv[r][0]=u.x; hv[r][1]=u.y; hv[r][2]=u.z; hv[r][3]=u.w;
        }
        #pragma unroll
        for (int dd=0; dd<4; dd++){
            float w0 = W1s[(d+dd)*65 + c2], w1 = W1s[(d+dd)*65 + c2 + 32];
            #pragma unroll
            for (int r=0;r<8;r++){
                acc[r][0] += hv[r][dd]*w0;
                acc[r][1] += hv[r][dd]*w1;
            }
        }
    }
    __syncthreads();
    #pragma unroll
    for (int r=0;r<8;r++)
        #pragma unroll
        for (int cc=0;cc<2;cc++){
            float z = acc[r][cc] + bs[c2 + 32*cc];
            hs[(rg*8+r)*68 + c2 + 32*cc] = 0.5f*z*(1.f + erff(z*0.7071067811865475f));
        }
    __syncthreads();

    float acc2[8][2];
    #pragma unroll
    for (int r=0;r<8;r++){ acc2[r][0]=0.f; acc2[r][1]=0.f; }
    #pragma unroll 4
    for (int d=0; d<64; d+=4){
        float hv[8][4];
        #pragma unroll
        for (int r=0;r<8;r++){
            float4 u = *(const float4*)(hs + (rg*8+r)*68 + d);
            hv[r][0]=u.x; hv[r][1]=u.y; hv[r][2]=u.z; hv[r][3]=u.w;
        }
        #pragma unroll
        for (int dd=0; dd<4; dd++){
            float w0 = W2s[(d+dd)*65 + c2], w1 = W2s[(d+dd)*65 + c2 + 32];
            #pragma unroll
            for (int r=0;r<8;r++){
                acc2[r][0] += hv[r][dd]*w0;
                acc2[r][1] += hv[r][dd]*w1;
            }
        }
    }
    int gt0 = blockIdx.x*64 + rg*8;
    #pragma unroll
    for (int r=0;r<8;r++)
        #pragma unroll
        for (int cc=0;cc<2;cc++){
            int col = c2 + 32*cc;
            g_x[((size_t)(gt0+r))*64 + col] = xs[(rg*8+r)*68 + col] + acc2[r][cc] + bs[64+col];
        }
}

// ============ 1x1 conv out + sigmoid ============
__global__ void k_out(const float* __restrict__ ow, const float* __restrict__ ob,
                      float* __restrict__ out){
    int id = blockIdx.x*256 + threadIdx.x;
    int t = id & (TT-1), b = id >> 12;
    const float4* xp = (const float4*)(g_x + (size_t)id*64);
    float a0 = __ldg(ob), a1 = __ldg(ob+1);
    #pragma unroll
    for (int d4=0; d4<16; d4++){
        float4 xv = xp[d4];
        a0 += xv.x*__ldg(ow+d4*4) + xv.y*__ldg(ow+d4*4+1) + xv.z*__ldg(ow+d4*4+2) + xv.w*__ldg(ow+d4*4+3);
        a1 += xv.x*__ldg(ow+64+d4*4) + xv.y*__ldg(ow+64+d4*4+1) + xv.z*__ldg(ow+64+d4*4+2) + xv.w*__ldg(ow+64+d4*4+3);
    }
    out[((size_t)(b*2))*TT + t]   = 1.f/(1.f+expf(-a0));
    out[((size_t)(b*2+1))*TT + t] = 1.f/(1.f+expf(-a1));
}

extern "C" void kernel_launch(void* const* d_in, const int* in_sizes, int n_in,
                              void* d_out, int out_size){
    const float* spec = (const float*)d_in[0];
    const float* c1w = (const float*)d_in[1];
    const float* c1b = (const float*)d_in[2];
    const float* c2w = (const float*)d_in[3];
    const float* c2b = (const float*)d_in[4];
    const float* c3w = (const float*)d_in[5];
    const float* c3b = (const float*)d_in[6];
    const float* Wq  = (const float*)d_in[7];
    const float* bq  = (const float*)d_in[8];
    const float* Wk  = (const float*)d_in[9];
    const float* bk  = (const float*)d_in[10];
    const float* Wv  = (const float*)d_in[11];
    const float* bv  = (const float*)d_in[12];
    const float* Er  = (const float*)d_in[13];
    const float* g1  = (const float*)d_in[14];
    const float* be1 = (const float*)d_in[15];
    const float* W1  = (const float*)d_in[16];
    const float* b1  = (const float*)d_in[17];
    const float* W2  = (const float*)d_in[18];
    const float* b2  = (const float*)d_in[19];
    const float* g2  = (const float*)d_in[20];
    const float* be2 = (const float*)d_in[21];
    const float* ow  = (const float*)d_in[22];
    const float* ob  = (const float*)d_in[23];

    cudaFuncSetAttribute(k_s2,  cudaFuncAttributeMaxDynamicSharedMemorySize, 65536);
    cudaFuncSetAttribute(k_s3,  cudaFuncAttributeMaxDynamicSharedMemorySize, 158208);
    cudaFuncSetAttribute(k_qkv, cudaFuncAttributeMaxDynamicSharedMemorySize, 84992);
    cudaFuncSetAttribute(k_attnff, cudaFuncAttributeMaxDynamicSharedMemorySize, 68608);

    k_s1<<<3328, 256>>>(spec, c1w, c1b);
    k_s2<<<dim3(64,8), 256, 65536>>>(c2w, c2b);
    k_s3<<<dim3(32,8), 512, 158208>>>(c3w, c3b);
    for (int L=0; L<11; L++){
        k_qkv<<<256, 512, 84992>>>(Wq+L*4096, bq+L*64, Wk+L*4096, bk+L*64,
                                   Wv+L*4096, bv+L*64, g1+L*64, be1+L*64);
        k_attnff<<<512, 256, 68608>>>(Er+L*384, 1<<L,
                                      W1+L*4096, b1+L*64, W2+L*4096, b2+L*64,
                                      g2+L*64, be2+L*64);
    }
    k_out<<<128, 256>>>(ow, ob, (float*)d_out);
}

// round 7
// speedup vs baseline: 1.1092x; 1.0223x over previous
#include <cuda_runtime.h>
#include <math.h>

#define TT 4096
#define NB 8
#define NBT (NB*TT)

__device__ __align__(256) float g_s1[NB*208*TT];
__device__ __align__(256) float g_s2[NB*160*TT];
__device__ __align__(256) float g_x [NBT*64];
__device__ __align__(256) float g_q [NBT*64];
__device__ __align__(256) float g_k [NBT*64];
__device__ __align__(256) float g_v [NBT*64];

// ============ stage 1: causal conv (1x3) + maxpool3(freq) + relu ============
__global__ void k_s1(const float* __restrict__ spec, const float* __restrict__ w,
                     const float* __restrict__ bias){
    int id = blockIdx.x*256 + threadIdx.x;
    int t  = id & (TT-1);
    int r  = id >> 12;
    int f2 = r % 26, b = r / 26;
    const float* sp = spec + (size_t)(b*81 + f2*3)*TT + t;
    float s[5][3];
    #pragma unroll
    for (int j=0;j<5;j++)
        #pragma unroll
        for (int i=0;i<3;i++)
            s[j][i] = (t+i < TT) ? sp[j*TT+i] : 0.f;
    #pragma unroll
    for (int c=0;c<8;c++){
        float a0=0.f,a1=0.f,a2=0.f;
        #pragma unroll
        for (int i=0;i<3;i++){
            if (t+i < TT){
                float w0=__ldg(w+(i*8+c)*3+0), w1=__ldg(w+(i*8+c)*3+1), w2=__ldg(w+(i*8+c)*3+2);
                float bb=__ldg(bias+i*8+c);
                a0 += bb + w0*s[0][i]+w1*s[1][i]+w2*s[2][i];
                a1 += bb + w0*s[1][i]+w1*s[2][i]+w2*s[3][i];
                a2 += bb + w0*s[2][i]+w1*s[3][i]+w2*s[4][i];
            }
        }
        float m = fmaxf(fmaxf(a0,a1),a2);
        g_s1[((size_t)(b*8+c)*26+f2)*TT + t] = fmaxf(m, 0.f);
    }
}

// ============ stage 2: conv (1x12) + maxpool3 + relu ============
__global__ void k_s2(const float* __restrict__ w2, const float* __restrict__ b2){
    extern __shared__ float sm[];
    float* s1s = sm;            // [208][64]
    float* ws  = sm + 208*64;   // 3072
    int tid = threadIdx.x, b = blockIdx.y, t0 = blockIdx.x*64;
    for (int i=tid; i<208*64; i+=256){
        int tl = i & 63, fr = i >> 6;
        s1s[i] = g_s1[((size_t)(b*208+fr))*TT + t0 + tl];
    }
    for (int i=tid; i<3072; i+=256) ws[i] = w2[i];
    __syncthreads();
    int tl = tid & 63, g = tid >> 6;
    for (int cb=0; cb<2; cb++){
        int co0 = g*8 + cb*4;
        float acc[4][5][3];
        #pragma unroll
        for (int u=0;u<4;u++){
            float bb = __ldg(b2 + co0 + u);
            #pragma unroll
            for (int f2=0;f2<5;f2++){ acc[u][f2][0]=bb; acc[u][f2][1]=bb; acc[u][f2][2]=bb; }
        }
        for (int cin=0; cin<8; cin++){
            float sv[26];
            #pragma unroll
            for (int ff=0; ff<26; ff++) sv[ff] = s1s[(cin*26+ff)*64 + tl];
            float w[4][12];
            #pragma unroll
            for (int u=0;u<4;u++)
                #pragma unroll
                for (int k=0;k<12;k++) w[u][k] = ws[(co0+u)*96 + cin*12 + k];
            #pragma unroll
            for (int f2=0; f2<5; f2++)
                #pragma unroll
                for (int k=0;k<12;k++)
                    #pragma unroll
                    for (int u=0;u<4;u++){
                        float wk = w[u][k];
                        acc[u][f2][0] += wk*sv[f2*3+k+0];
                        acc[u][f2][1] += wk*sv[f2*3+k+1];
                        acc[u][f2][2] += wk*sv[f2*3+k+2];
                    }
        }
        #pragma unroll
        for (int u=0;u<4;u++)
            #pragma unroll
            for (int f2=0;f2<5;f2++){
                float m = fmaxf(fmaxf(acc[u][f2][0],acc[u][f2][1]),acc[u][f2][2]);
                g_s2[((size_t)((b*32+co0+u)*5+f2))*TT + t0 + tl] = fmaxf(m, 0.f);
            }
    }
}

// ============ stage 3: causal conv (1x3, cin32,co64) + maxpool3 + relu ============
__global__ void __launch_bounds__(512) k_s3(const float* __restrict__ w3, const float* __restrict__ b3){
    extern __shared__ float sm[];
    float* s2s = sm;              // [160][132]
    float* w3s = sm + 160*132;    // 18432
    int tid = threadIdx.x, b = blockIdx.y, t0 = blockIdx.x*128;
    for (int i=tid; i<160*132; i+=512){
        int tl = i % 132, fr = i / 132;
        int tg = t0 + tl;
        s2s[i] = (tg < TT && tl < 130) ? g_s2[((size_t)(b*160+fr))*TT + tg] : 0.f;
    }
    for (int i=tid; i<18432; i+=512){
        int co = i & 63, r = i >> 6;
        int k = r % 3; r /= 3;
        int cin = r & 31, ii = r >> 5;
        w3s[i] = w3[((size_t)(ii*64+co)*32+cin)*3 + k];
    }
    __syncthreads();
    int co = tid & 63, tg8 = tid >> 6;
    float bb0 = __ldg(b3+co), bb1 = __ldg(b3+64+co), bb2 = __ldg(b3+128+co);
    for (int chunk=0; chunk<2; chunk++){
        int tlbase = tg8*16 + chunk*8;
        float acc[8][3];
        #pragma unroll
        for (int rr=0;rr<8;rr++){ acc[rr][0]=0.f; acc[rr][1]=0.f; acc[rr][2]=0.f; }
        for (int cin=0; cin<32; cin++){
            float sv[5][12];
            #pragma unroll
            for (int ff=0; ff<5; ff++){
                const float4* p = (const float4*)(s2s + (cin*5+ff)*132 + tlbase);
                float4 u0=p[0], u1=p[1], u2=p[2];
                sv[ff][0]=u0.x; sv[ff][1]=u0.y; sv[ff][2]=u0.z; sv[ff][3]=u0.w;
                sv[ff][4]=u1.x; sv[ff][5]=u1.y; sv[ff][6]=u1.z; sv[ff][7]=u1.w;
                sv[ff][8]=u2.x; sv[ff][9]=u2.y; sv[ff][10]=u2.z; sv[ff][11]=u2.w;
            }
            #pragma unroll
            for (int ii=0; ii<3; ii++)
                #pragma unroll
                for (int k=0; k<3; k++){
                    float wk = w3s[((ii*32+cin)*3+k)*64 + co];
                    #pragma unroll
                    for (int f=0; f<3; f++)
                        #pragma unroll
                        for (int rr=0; rr<8; rr++)
                            acc[rr][f] += wk*sv[f+k][rr+ii];
                }
        }
        #pragma unroll
        for (int rr=0; rr<8; rr++){
            int tg = t0 + tlbase + rr;
            float a0=acc[rr][0]+bb0, a1=acc[rr][1]+bb0, a2=acc[rr][2]+bb0;
            if (tg+1 < TT){ a0+=bb1; a1+=bb1; a2+=bb1; }
            if (tg+2 < TT){ a0+=bb2; a1+=bb2; a2+=bb2; }
            float m = fmaxf(fmaxf(a0,a1),a2);
            g_x[((size_t)(b*TT+tg))*64 + co] = fmaxf(m, 0.f);
        }
    }
}

// ============ LN1 + QKV projection (64 tokens/block, 8x6 reg tiles, paired cols) ============
__global__ void __launch_bounds__(256, 2) k_qkv(
        const float* __restrict__ Wq, const float* __restrict__ bq,
        const float* __restrict__ Wk, const float* __restrict__ bk,
        const float* __restrict__ Wv, const float* __restrict__ bv,
        const float* __restrict__ gam, const float* __restrict__ bet){
    extern __shared__ float sm[];
    float* Ws = sm;               // [64][194]  cols 0..63=Q, 64..127=K, 128..191=V
    float* bs = sm + 64*194;      // 192
    float* hs = bs + 192;         // [64][68]
    int tid = threadIdx.x;
    for (int i=tid; i<4096; i+=256){
        int col = i >> 6, d = i & 63;
        Ws[d*194 + col]       = Wq[i];
        Ws[d*194 + 64 + col]  = Wk[i];
        Ws[d*194 + 128 + col] = Wv[i];
    }
    if (tid < 64){ bs[tid]=bq[tid]; bs[64+tid]=bk[tid]; bs[128+tid]=bv[tid]; }
    int tok = tid >> 2, lane = tid & 3;
    int gtok = blockIdx.x*64 + tok;
    const float* xr = g_x + (size_t)gtok*64 + lane*16;
    float v[16];
    #pragma unroll
    for (int c=0;c<4;c++){
        float4 u = *(const float4*)(xr + c*4);
        v[c*4]=u.x; v[c*4+1]=u.y; v[c*4+2]=u.z; v[c*4+3]=u.w;
    }
    float s=0.f, ss=0.f;
    #pragma unroll
    for (int m=0;m<16;m++){ s += v[m]; ss += v[m]*v[m]; }
    s += __shfl_xor_sync(0xffffffffu,s,1); ss += __shfl_xor_sync(0xffffffffu,ss,1);
    s += __shfl_xor_sync(0xffffffffu,s,2); ss += __shfl_xor_sync(0xffffffffu,ss,2);
    float mean = s*(1.f/64.f);
    float var  = ss*(1.f/64.f) - mean*mean;
    float rstd = rsqrtf(fmaxf(var,0.f) + 1e-5f);
    #pragma unroll
    for (int m=0;m<16;m++){
        int dd = lane*16+m;
        hs[tok*68+dd] = (v[m]-mean)*rstd*__ldg(gam+dd) + __ldg(bet+dd);
    }
    __syncthreads();
    // GEMM: 32 lanes x 8 rowgroups; thread covers 8 tokens x (3 segs x 2 adj cols)
    int x32 = tid & 31, rg = tid >> 5;
    float acc[8][3][2];
    #pragma unroll
    for (int r=0;r<8;r++)
        #pragma unroll
        for (int sg=0;sg<3;sg++){ acc[r][sg][0]=0.f; acc[r][sg][1]=0.f; }
    #pragma unroll 4
    for (int d=0; d<64; d+=4){
        float hv[8][4];
        #pragma unroll
        for (int r=0;r<8;r++){
            float4 u = *(const float4*)(hs + (rg*8+r)*68 + d);
            hv[r][0]=u.x; hv[r][1]=u.y; hv[r][2]=u.z; hv[r][3]=u.w;
        }
        #pragma unroll
        for (int dd=0; dd<4; dd++){
            float2 w0 = *(const float2*)(Ws + (d+dd)*194 + 2*x32);
            float2 w1 = *(const float2*)(Ws + (d+dd)*194 + 64 + 2*x32);
            float2 w2 = *(const float2*)(Ws + (d+dd)*194 + 128 + 2*x32);
            #pragma unroll
            for (int r=0;r<8;r++){
                float h = hv[r][dd];
                acc[r][0][0] += h*w0.x; acc[r][0][1] += h*w0.y;
                acc[r][1][0] += h*w1.x; acc[r][1][1] += h*w1.y;
                acc[r][2][0] += h*w2.x; acc[r][2][1] += h*w2.y;
            }
        }
    }
    int gt0 = blockIdx.x*64 + rg*8;
    #pragma unroll
    for (int r=0;r<8;r++){
        #pragma unroll
        for (int sg=0;sg<3;sg++){
            float* dst = (sg==0) ? g_q : (sg==1) ? g_k : g_v;
            float2 val;
            val.x = acc[r][sg][0] + bs[sg*64 + 2*x32];
            val.y = acc[r][sg][1] + bs[sg*64 + 2*x32 + 1];
            *(float2*)(dst + ((size_t)(gt0+r))*64 + 2*x32) = val;
        }
    }
}

// ============ attention + residual + LN2 + FF + residual (fused) ============
__global__ void __launch_bounds__(256) k_attnff(
        const float* __restrict__ Er, int shift,
        const float* __restrict__ W1p, const float* __restrict__ b1p,
        const float* __restrict__ W2p, const float* __restrict__ b2p,
        const float* __restrict__ gam, const float* __restrict__ bet){
    extern __shared__ float sm[];
    float* W1s = sm;            // [64][66]
    float* W2s = sm + 4224;     // [64][66]
    float* bs  = sm + 8448;     // 128
    float* xs  = sm + 8576;     // [64][68]
    float* hs  = sm + 12928;    // [64][68]
    int tid = threadIdx.x;
    for (int i=tid; i<4096; i+=256){
        int col = i >> 6, d = i & 63;
        W1s[d*66+col] = W1p[i];
        W2s[d*66+col] = W2p[i];
    }
    if (tid < 64){ bs[tid]=b1p[tid]; bs[64+tid]=b2p[tid]; }

    {
        int tok = tid >> 2, hp = (tid & 3)*2;
        int gtok = blockIdx.x*64 + tok;
        int b = gtok >> 12, t = gtok & (TT-1);
        size_t bt = (size_t)b*TT + t;
        int sh[6]; sh[0]=0; sh[1]=0; sh[2]=shift; sh[3]=2*shift; sh[4]=3*shift; sh[5]=4*shift;
        #pragma unroll
        for (int hh=0; hh<2; hh++){
            int h = hp + hh;
            const float* qp = g_q + bt*64 + h*8;
            float4 q0 = *(const float4*)qp, q1 = *(const float4*)(qp+4);
            float q[8] = {q0.x,q0.y,q0.z,q0.w,q1.x,q1.y,q1.z,q1.w};
            const float* er = Er + h*48;
            float lg[6];
            #pragma unroll
            for (int j=0;j<6;j++){
                float qe = 0.f;
                #pragma unroll
                for (int d=0;d<8;d++) qe += q[d]*__ldg(er + d*6 + j);
                lg[j] = qe;
            }
            #pragma unroll
            for (int j=0;j<6;j++){
                int tp = t - sh[j];
                float qk = 0.f;
                if (tp >= 0){
                    const float* kp = g_k + ((size_t)b*TT+tp)*64 + h*8;
                    float4 k0 = *(const float4*)kp, k1 = *(const float4*)(kp+4);
                    qk = q[0]*k0.x + q[1]*k0.y + q[2]*k0.z + q[3]*k0.w
                       + q[4]*k1.x + q[5]*k1.y + q[6]*k1.z + q[7]*k1.w;
                }
                lg[j] = (qk + lg[j]) * 0.3535533905932738f;
            }
            float mx = lg[0];
            #pragma unroll
            for (int j=1;j<6;j++) mx = fmaxf(mx, lg[j]);
            float e[6], se = 0.f;
            #pragma unroll
            for (int j=0;j<6;j++){ e[j] = expf(lg[j]-mx); se += e[j]; }
            float inv = 1.f/se;
            float o[8] = {0,0,0,0,0,0,0,0};
            #pragma unroll
            for (int j=0;j<6;j++){
                int tp = t - sh[j];
                if (tp >= 0){
                    const float* vp = g_v + ((size_t)b*TT+tp)*64 + h*8;
                    float4 v0 = *(const float4*)vp, v1 = *(const float4*)(vp+4);
                    float a = e[j];
                    o[0]+=a*v0.x; o[1]+=a*v0.y; o[2]+=a*v0.z; o[3]+=a*v0.w;
                    o[4]+=a*v1.x; o[5]+=a*v1.y; o[6]+=a*v1.z; o[7]+=a*v1.w;
                }
            }
            const float* xp = g_x + (size_t)gtok*64 + h*8;
            float4 x0 = *(const float4*)xp, x1 = *(const float4*)(xp+4);
            float* xd = xs + tok*68 + h*8;
            xd[0]=x0.x+o[0]*inv; xd[1]=x0.y+o[1]*inv; xd[2]=x0.z+o[2]*inv; xd[3]=x0.w+o[3]*inv;
            xd[4]=x1.x+o[4]*inv; xd[5]=x1.y+o[5]*inv; xd[6]=x1.z+o[6]*inv; xd[7]=x1.w+o[7]*inv;
        }
    }
    __syncthreads();

    {
        int tok = tid >> 2, lane = tid & 3;
        float v[16];
        #pragma unroll
        for (int m=0;m<16;m++) v[m] = xs[tok*68 + lane*16 + m];
        float s=0.f, ss=0.f;
        #pragma unroll
        for (int m=0;m<16;m++){ s += v[m]; ss += v[m]*v[m]; }
        s += __shfl_xor_sync(0xffffffffu,s,1); ss += __shfl_xor_sync(0xffffffffu,ss,1);
        s += __shfl_xor_sync(0xffffffffu,s,2); ss += __shfl_xor_sync(0xffffffffu,ss,2);
        float mean = s*(1.f/64.f);
        float var  = ss*(1.f/64.f) - mean*mean;
        float rstd = rsqrtf(fmaxf(var,0.f) + 1e-5f);
        #pragma unroll
        for (int m=0;m<16;m++){
            int dd = lane*16+m;
            hs[tok*68+dd] = (v[m]-mean)*rstd*__ldg(gam+dd) + __ldg(bet+dd);
        }
    }
    __syncthreads();

    // GEMM1: paired adjacent cols 2*c2, 2*c2+1
    int c2 = tid & 31, rg = tid >> 5;
    float acc[8][2];
    #pragma unroll
    for (int r=0;r<8;r++){ acc[r][0]=0.f; acc[r][1]=0.f; }
    #pragma unroll 4
    for (int d=0; d<64; d+=4){
        float hv[8][4];
        #pragma unroll
        for (int r=0;r<8;r++){
            float4 u = *(const float4*)(hs + (rg*8+r)*68 + d);
            hv[r][0]=u.x; hv[r][1]=u.y; hv[r][2]=u.z; hv[r][3]=u.w;
        }
        #pragma unroll
        for (int dd=0; dd<4; dd++){
            float2 w01 = *(const float2*)(W1s + (d+dd)*66 + 2*c2);
            #pragma unroll
            for (int r=0;r<8;r++){
                acc[r][0] += hv[r][dd]*w01.x;
                acc[r][1] += hv[r][dd]*w01.y;
            }
        }
    }
    __syncthreads();
    #pragma unroll
    for (int r=0;r<8;r++)
        #pragma unroll
        for (int e=0;e<2;e++){
            float z = acc[r][e] + bs[2*c2 + e];
            hs[(rg*8+r)*68 + 2*c2 + e] = 0.5f*z*(1.f + erff(z*0.7071067811865475f));
        }
    __syncthreads();

    float acc2[8][2];
    #pragma unroll
    for (int r=0;r<8;r++){ acc2[r][0]=0.f; acc2[r][1]=0.f; }
    #pragma unroll 4
    for (int d=0; d<64; d+=4){
        float hv[8][4];
        #pragma unroll
        for (int r=0;r<8;r++){
            float4 u = *(const float4*)(hs + (rg*8+r)*68 + d);
            hv[r][0]=u.x; hv[r][1]=u.y; hv[r][2]=u.z; hv[r][3]=u.w;
        }
        #pragma unroll
        for (int dd=0; dd<4; dd++){
            float2 w01 = *(const float2*)(W2s + (d+dd)*66 + 2*c2);
            #pragma unroll
            for (int r=0;r<8;r++){
                acc2[r][0] += hv[r][dd]*w01.x;
                acc2[r][1] += hv[r][dd]*w01.y;
            }
        }
    }
    int gt0 = blockIdx.x*64 + rg*8;
    #pragma unroll
    for (int r=0;r<8;r++){
        float2 val;
        val.x = xs[(rg*8+r)*68 + 2*c2]     + acc2[r][0] + bs[64 + 2*c2];
        val.y = xs[(rg*8+r)*68 + 2*c2 + 1] + acc2[r][1] + bs[64 + 2*c2 + 1];
        *(float2*)(g_x + ((size_t)(gt0+r))*64 + 2*c2) = val;
    }
}

// ============ 1x1 conv out + sigmoid ============
__global__ void k_out(const float* __restrict__ ow, const float* __restrict__ ob,
                      float* __restrict__ out){
    int id = blockIdx.x*256 + threadIdx.x;
    int t = id & (TT-1), b = id >> 12;
    const float4* xp = (const float4*)(g_x + (size_t)id*64);
    float a0 = __ldg(ob), a1 = __ldg(ob+1);
    #pragma unroll
    for (int d4=0; d4<16; d4++){
        float4 xv = xp[d4];
        a0 += xv.x*__ldg(ow+d4*4) + xv.y*__ldg(ow+d4*4+1) + xv.z*__ldg(ow+d4*4+2) + xv.w*__ldg(ow+d4*4+3);
        a1 += xv.x*__ldg(ow+64+d4*4) + xv.y*__ldg(ow+64+d4*4+1) + xv.z*__ldg(ow+64+d4*4+2) + xv.w*__ldg(ow+64+d4*4+3);
    }
    out[((size_t)(b*2))*TT + t]   = 1.f/(1.f+expf(-a0));
    out[((size_t)(b*2+1))*TT + t] = 1.f/(1.f+expf(-a1));
}

extern "C" void kernel_launch(void* const* d_in, const int* in_sizes, int n_in,
                              void* d_out, int out_size){
    const float* spec = (const float*)d_in[0];
    const float* c1w = (const float*)d_in[1];
    const float* c1b = (const float*)d_in[2];
    const float* c2w = (const float*)d_in[3];
    const float* c2b = (const float*)d_in[4];
    const float* c3w = (const float*)d_in[5];
    const float* c3b = (const float*)d_in[6];
    const float* Wq  = (const float*)d_in[7];
    const float* bq  = (const float*)d_in[8];
    const float* Wk  = (const float*)d_in[9];
    const float* bk  = (const float*)d_in[10];
    const float* Wv  = (const float*)d_in[11];
    const float* bv  = (const float*)d_in[12];
    const float* Er  = (const float*)d_in[13];
    const float* g1  = (const float*)d_in[14];
    const float* be1 = (const float*)d_in[15];
    const float* W1  = (const float*)d_in[16];
    const float* b1  = (const float*)d_in[17];
    const float* W2  = (const float*)d_in[18];
    const float* b2  = (const float*)d_in[19];
    const float* g2  = (const float*)d_in[20];
    const float* be2 = (const float*)d_in[21];
    const float* ow  = (const float*)d_in[22];
    const float* ob  = (const float*)d_in[23];

    cudaFuncSetAttribute(k_s2,  cudaFuncAttributeMaxDynamicSharedMemorySize, 65536);
    cudaFuncSetAttribute(k_s3,  cudaFuncAttributeMaxDynamicSharedMemorySize, 158208);
    cudaFuncSetAttribute(k_qkv, cudaFuncAttributeMaxDynamicSharedMemorySize, 67840);
    cudaFuncSetAttribute(k_attnff, cudaFuncAttributeMaxDynamicSharedMemorySize, 69120);

    k_s1<<<3328, 256>>>(spec, c1w, c1b);
    k_s2<<<dim3(64,8), 256, 65536>>>(c2w, c2b);
    k_s3<<<dim3(32,8), 512, 158208>>>(c3w, c3b);
    for (int L=0; L<11; L++){
        k_qkv<<<512, 256, 67840>>>(Wq+L*4096, bq+L*64, Wk+L*4096, bk+L*64,
                                   Wv+L*4096, bv+L*64, g1+L*64, be1+L*64);
        k_attnff<<<512, 256, 69120>>>(Er+L*384, 1<<L,
                                      W1+L*4096, b1+L*64, W2+L*4096, b2+L*64,
                                      g2+L*64, be2+L*64);
    }
    k_out<<<128, 256>>>(ow, ob, (float*)d_out);
}

// round 9
// speedup vs baseline: 1.1992x; 1.0812x over previous
#include <cuda_runtime.h>
#include <math.h>

#define TT 4096
#define NB 8
#define NBT (NB*TT)

__device__ __align__(256) float g_s1[NB*208*TT];
__device__ __align__(256) float g_s2[NB*160*TT];
__device__ __align__(256) float g_x [NBT*64];
__device__ __align__(256) float g_q [NBT*64];
__device__ __align__(256) float g_k [NBT*64];
__device__ __align__(256) float g_v [NBT*64];

// ============ stage 1: causal conv (1x3) + maxpool3(freq) + relu ============
__global__ void k_s1(const float* __restrict__ spec, const float* __restrict__ w,
                     const float* __restrict__ bias){
    int id = blockIdx.x*256 + threadIdx.x;
    int t  = id & (TT-1);
    int r  = id >> 12;
    int f2 = r % 26, b = r / 26;
    const float* sp = spec + (size_t)(b*81 + f2*3)*TT + t;
    float s[5][3];
    #pragma unroll
    for (int j=0;j<5;j++)
        #pragma unroll
        for (int i=0;i<3;i++)
            s[j][i] = (t+i < TT) ? sp[j*TT+i] : 0.f;
    #pragma unroll
    for (int c=0;c<8;c++){
        float a0=0.f,a1=0.f,a2=0.f;
        #pragma unroll
        for (int i=0;i<3;i++){
            if (t+i < TT){
                float w0=__ldg(w+(i*8+c)*3+0), w1=__ldg(w+(i*8+c)*3+1), w2=__ldg(w+(i*8+c)*3+2);
                float bb=__ldg(bias+i*8+c);
                a0 += bb + w0*s[0][i]+w1*s[1][i]+w2*s[2][i];
                a1 += bb + w0*s[1][i]+w1*s[2][i]+w2*s[3][i];
                a2 += bb + w0*s[2][i]+w1*s[3][i]+w2*s[4][i];
            }
        }
        float m = fmaxf(fmaxf(a0,a1),a2);
        g_s1[((size_t)(b*8+c)*26+f2)*TT + t] = fmaxf(m, 0.f);
    }
}

// ============ stage 2: conv (1x12) + maxpool3 + relu ============
__global__ void k_s2(const float* __restrict__ w2, const float* __restrict__ b2){
    extern __shared__ float sm[];
    float* s1s = sm;            // [208][64]
    float* ws  = sm + 208*64;   // 3072
    int tid = threadIdx.x, b = blockIdx.y, t0 = blockIdx.x*64;
    for (int i=tid; i<208*64; i+=256){
        int tl = i & 63, fr = i >> 6;
        s1s[i] = g_s1[((size_t)(b*208+fr))*TT + t0 + tl];
    }
    for (int i=tid; i<3072; i+=256) ws[i] = w2[i];
    __syncthreads();
    int tl = tid & 63, g = tid >> 6;
    for (int cb=0; cb<2; cb++){
        int co0 = g*8 + cb*4;
        float acc[4][5][3];
        #pragma unroll
        for (int u=0;u<4;u++){
            float bb = __ldg(b2 + co0 + u);
            #pragma unroll
            for (int f2=0;f2<5;f2++){ acc[u][f2][0]=bb; acc[u][f2][1]=bb; acc[u][f2][2]=bb; }
        }
        for (int cin=0; cin<8; cin++){
            float sv[26];
            #pragma unroll
            for (int ff=0; ff<26; ff++) sv[ff] = s1s[(cin*26+ff)*64 + tl];
            float w[4][12];
            #pragma unroll
            for (int u=0;u<4;u++)
                #pragma unroll
                for (int k=0;k<12;k++) w[u][k] = ws[(co0+u)*96 + cin*12 + k];
            #pragma unroll
            for (int f2=0; f2<5; f2++)
                #pragma unroll
                for (int k=0;k<12;k++)
                    #pragma unroll
                    for (int u=0;u<4;u++){
                        float wk = w[u][k];
                        acc[u][f2][0] += wk*sv[f2*3+k+0];
                        acc[u][f2][1] += wk*sv[f2*3+k+1];
                        acc[u][f2][2] += wk*sv[f2*3+k+2];
                    }
        }
        #pragma unroll
        for (int u=0;u<4;u++)
            #pragma unroll
            for (int f2=0;f2<5;f2++){
                float m = fmaxf(fmaxf(acc[u][f2][0],acc[u][f2][1]),acc[u][f2][2]);
                g_s2[((size_t)((b*32+co0+u)*5+f2))*TT + t0 + tl] = fmaxf(m, 0.f);
            }
    }
}

// ============ stage 3: causal conv (1x3, cin32,co64) + maxpool3 + relu ============
__global__ void __launch_bounds__(512) k_s3(const float* __restrict__ w3, const float* __restrict__ b3){
    extern __shared__ float sm[];
    float* s2s = sm;              // [160][132]
    float* w3s = sm + 160*132;    // 18432
    int tid = threadIdx.x, b = blockIdx.y, t0 = blockIdx.x*128;
    for (int i=tid; i<160*132; i+=512){
        int tl = i % 132, fr = i / 132;
        int tg = t0 + tl;
        s2s[i] = (tg < TT && tl < 130) ? g_s2[((size_t)(b*160+fr))*TT + tg] : 0.f;
    }
    for (int i=tid; i<18432; i+=512){
        int co = i & 63, r = i >> 6;
        int k = r % 3; r /= 3;
        int cin = r & 31, ii = r >> 5;
        w3s[i] = w3[((size_t)(ii*64+co)*32+cin)*3 + k];
    }
    __syncthreads();
    int co = tid & 63, tg8 = tid >> 6;
    float bb0 = __ldg(b3+co), bb1 = __ldg(b3+64+co), bb2 = __ldg(b3+128+co);
    for (int chunk=0; chunk<2; chunk++){
        int tlbase = tg8*16 + chunk*8;
        float acc[8][3];
        #pragma unroll
        for (int rr=0;rr<8;rr++){ acc[rr][0]=0.f; acc[rr][1]=0.f; acc[rr][2]=0.f; }
        for (int cin=0; cin<32; cin++){
            float sv[5][12];
            #pragma unroll
            for (int ff=0; ff<5; ff++){
                const float4* p = (const float4*)(s2s + (cin*5+ff)*132 + tlbase);
                float4 u0=p[0], u1=p[1], u2=p[2];
                sv[ff][0]=u0.x; sv[ff][1]=u0.y; sv[ff][2]=u0.z; sv[ff][3]=u0.w;
                sv[ff][4]=u1.x; sv[ff][5]=u1.y; sv[ff][6]=u1.z; sv[ff][7]=u1.w;
                sv[ff][8]=u2.x; sv[ff][9]=u2.y; sv[ff][10]=u2.z; sv[ff][11]=u2.w;
            }
            #pragma unroll
            for (int ii=0; ii<3; ii++)
                #pragma unroll
                for (int k=0; k<3; k++){
                    float wk = w3s[((ii*32+cin)*3+k)*64 + co];
                    #pragma unroll
                    for (int f=0; f<3; f++)
                        #pragma unroll
                        for (int rr=0; rr<8; rr++)
                            acc[rr][f] += wk*sv[f+k][rr+ii];
                }
        }
        #pragma unroll
        for (int rr=0; rr<8; rr++){
            int tg = t0 + tlbase + rr;
            float a0=acc[rr][0]+bb0, a1=acc[rr][1]+bb0, a2=acc[rr][2]+bb0;
            if (tg+1 < TT){ a0+=bb1; a1+=bb1; a2+=bb1; }
            if (tg+2 < TT){ a0+=bb2; a1+=bb2; a2+=bb2; }
            float m = fmaxf(fmaxf(a0,a1),a2);
            g_x[((size_t)(b*TT+tg))*64 + co] = fmaxf(m, 0.f);
        }
    }
}

// ============ LN1 + QKV projection (64 tokens/block, 512 thr, 4x6 tiles) ============
__global__ void __launch_bounds__(512, 2) k_qkv(
        const float* __restrict__ Wq, const float* __restrict__ bq,
        const float* __restrict__ Wk, const float* __restrict__ bk,
        const float* __restrict__ Wv, const float* __restrict__ bv,
        const float* __restrict__ gam, const float* __restrict__ bet){
    extern __shared__ float sm[];
    float* Ws = sm;               // [64][194]
    float* bs = sm + 64*194;      // 192
    float* hs = bs + 192;         // [64][68]
    int tid = threadIdx.x;
    for (int i=tid; i<4096; i+=512){
        int col = i >> 6, d = i & 63;
        Ws[d*194 + col]       = Wq[i];
        Ws[d*194 + 64 + col]  = Wk[i];
        Ws[d*194 + 128 + col] = Wv[i];
    }
    if (tid < 64){ bs[tid]=bq[tid]; bs[64+tid]=bk[tid]; bs[128+tid]=bv[tid]; }
    // LN: 8 threads per token, 8 dims each
    int tok = tid >> 3, lane = tid & 7;
    int gtok = blockIdx.x*64 + tok;
    const float* xr = g_x + (size_t)gtok*64 + lane*8;
    float4 u0 = *(const float4*)xr, u1 = *(const float4*)(xr+4);
    float v[8] = {u0.x,u0.y,u0.z,u0.w,u1.x,u1.y,u1.z,u1.w};
    float s=0.f, ss=0.f;
    #pragma unroll
    for (int m=0;m<8;m++){ s += v[m]; ss += v[m]*v[m]; }
    s += __shfl_xor_sync(0xffffffffu,s,1); ss += __shfl_xor_sync(0xffffffffu,ss,1);
    s += __shfl_xor_sync(0xffffffffu,s,2); ss += __shfl_xor_sync(0xffffffffu,ss,2);
    s += __shfl_xor_sync(0xffffffffu,s,4); ss += __shfl_xor_sync(0xffffffffu,ss,4);
    float mean = s*(1.f/64.f);
    float var  = ss*(1.f/64.f) - mean*mean;
    float rstd = rsqrtf(fmaxf(var,0.f) + 1e-5f);
    #pragma unroll
    for (int m=0;m<8;m++){
        int dd = lane*8+m;
        hs[tok*68+dd] = (v[m]-mean)*rstd*__ldg(gam+dd) + __ldg(bet+dd);
    }
    __syncthreads();
    // GEMM: 32 lanes x 16 rowgroups; 4 tokens x (3 segs x 2 adj cols)
    int x32 = tid & 31, rg = tid >> 5;
    float acc[4][3][2];
    #pragma unroll
    for (int r=0;r<4;r++)
        #pragma unroll
        for (int sg=0;sg<3;sg++){ acc[r][sg][0]=0.f; acc[r][sg][1]=0.f; }
    #pragma unroll 4
    for (int d=0; d<64; d+=4){
        float hv[4][4];
        #pragma unroll
        for (int r=0;r<4;r++){
            float4 u = *(const float4*)(hs + (rg*4+r)*68 + d);
            hv[r][0]=u.x; hv[r][1]=u.y; hv[r][2]=u.z; hv[r][3]=u.w;
        }
        #pragma unroll
        for (int dd=0; dd<4; dd++){
            float2 w0 = *(const float2*)(Ws + (d+dd)*194 + 2*x32);
            float2 w1 = *(const float2*)(Ws + (d+dd)*194 + 64 + 2*x32);
            float2 w2 = *(const float2*)(Ws + (d+dd)*194 + 128 + 2*x32);
            #pragma unroll
            for (int r=0;r<4;r++){
                float h = hv[r][dd];
                acc[r][0][0] += h*w0.x; acc[r][0][1] += h*w0.y;
                acc[r][1][0] += h*w1.x; acc[r][1][1] += h*w1.y;
                acc[r][2][0] += h*w2.x; acc[r][2][1] += h*w2.y;
            }
        }
    }
    int gt0 = blockIdx.x*64 + rg*4;
    #pragma unroll
    for (int r=0;r<4;r++){
        #pragma unroll
        for (int sg=0;sg<3;sg++){
            float* dst = (sg==0) ? g_q : (sg==1) ? g_k : g_v;
            float2 val;
            val.x = acc[r][sg][0] + bs[sg*64 + 2*x32];
            val.y = acc[r][sg][1] + bs[sg*64 + 2*x32 + 1];
            *(float2*)(dst + ((size_t)(gt0+r))*64 + 2*x32) = val;
        }
    }
}

// ============ attention + residual + LN2 + FF + residual (fused, 512 thr) ============
__global__ void __launch_bounds__(512, 2) k_attnff(
        const float* __restrict__ Er, int shift,
        const float* __restrict__ W1p, const float* __restrict__ b1p,
        const float* __restrict__ W2p, const float* __restrict__ b2p,
        const float* __restrict__ gam, const float* __restrict__ bet){
    extern __shared__ float sm[];
    float* W1s = sm;            // [64][66]
    float* W2s = sm + 4224;     // [64][66]
    float* bs  = sm + 8448;     // 128
    float* xs  = sm + 8576;     // [64][68]
    float* hs  = sm + 12928;    // [64][68]
    int tid = threadIdx.x;
    for (int i=tid; i<4096; i+=512){
        int col = i >> 6, d = i & 63;
        W1s[d*66+col] = W1p[i];
        W2s[d*66+col] = W2p[i];
    }
    if (tid < 64){ bs[tid]=b1p[tid]; bs[64+tid]=b2p[tid]; }

    // ---- attention: 8 threads/token, 1 head each ----
    {
        int tok = tid >> 3, h = tid & 7;
        int gtok = blockIdx.x*64 + tok;
        int b = gtok >> 12, t = gtok & (TT-1);
        size_t bt = (size_t)b*TT + t;
        int sh[6]; sh[0]=0; sh[1]=0; sh[2]=shift; sh[3]=2*shift; sh[4]=3*shift; sh[5]=4*shift;
        const float* qp = g_q + bt*64 + h*8;
        float4 q0 = *(const float4*)qp, q1 = *(const float4*)(qp+4);
        float q[8] = {q0.x,q0.y,q0.z,q0.w,q1.x,q1.y,q1.z,q1.w};
        const float* er = Er + h*48;
        float lg[6];
        #pragma unroll
        for (int j=0;j<6;j++){
            float qe = 0.f;
            #pragma unroll
            for (int d=0;d<8;d++) qe += q[d]*__ldg(er + d*6 + j);
            lg[j] = qe;
        }
        #pragma unroll
        for (int j=0;j<6;j++){
            int tp = t - sh[j];
            float qk = 0.f;
            if (tp >= 0){
                const float* kp = g_k + ((size_t)b*TT+tp)*64 + h*8;
                float4 k0 = *(const float4*)kp, k1 = *(const float4*)(kp+4);
                qk = q[0]*k0.x + q[1]*k0.y + q[2]*k0.z + q[3]*k0.w
                   + q[4]*k1.x + q[5]*k1.y + q[6]*k1.z + q[7]*k1.w;
            }
            lg[j] = (qk + lg[j]) * 0.3535533905932738f;
        }
        float mx = lg[0];
        #pragma unroll
        for (int j=1;j<6;j++) mx = fmaxf(mx, lg[j]);
        float e[6], se = 0.f;
        #pragma unroll
        for (int j=0;j<6;j++){ e[j] = expf(lg[j]-mx); se += e[j]; }
        float inv = 1.f/se;
        float o[8] = {0,0,0,0,0,0,0,0};
        #pragma unroll
        for (int j=0;j<6;j++){
            int tp = t - sh[j];
            if (tp >= 0){
                const float* vp = g_v + ((size_t)b*TT+tp)*64 + h*8;
                float4 v0 = *(const float4*)vp, v1 = *(const float4*)(vp+4);
                float a = e[j];
                o[0]+=a*v0.x; o[1]+=a*v0.y; o[2]+=a*v0.z; o[3]+=a*v0.w;
                o[4]+=a*v1.x; o[5]+=a*v1.y; o[6]+=a*v1.z; o[7]+=a*v1.w;
            }
        }
        const float* xp = g_x + (size_t)gtok*64 + h*8;
        float4 x0 = *(const float4*)xp, x1 = *(const float4*)(xp+4);
        float* xd = xs + tok*68 + h*8;
        xd[0]=x0.x+o[0]*inv; xd[1]=x0.y+o[1]*inv; xd[2]=x0.z+o[2]*inv; xd[3]=x0.w+o[3]*inv;
        xd[4]=x1.x+o[4]*inv; xd[5]=x1.y+o[5]*inv; xd[6]=x1.z+o[6]*inv; xd[7]=x1.w+o[7]*inv;
    }
    __syncthreads();

    // ---- LN2: 8 threads/token ----
    {
        int tok = tid >> 3, lane = tid & 7;
        float v[8];
        #pragma unroll
        for (int m=0;m<8;m++) v[m] = xs[tok*68 + lane*8 + m];
        float s=0.f, ss=0.f;
        #pragma unroll
        for (int m=0;m<8;m++){ s += v[m]; ss += v[m]*v[m]; }
        s += __shfl_xor_sync(0xffffffffu,s,1); ss += __shfl_xor_sync(0xffffffffu,ss,1);
        s += __shfl_xor_sync(0xffffffffu,s,2); ss += __shfl_xor_sync(0xffffffffu,ss,2);
        s += __shfl_xor_sync(0xffffffffu,s,4); ss += __shfl_xor_sync(0xffffffffu,ss,4);
        float mean = s*(1.f/64.f);
        float var  = ss*(1.f/64.f) - mean*mean;
        float rstd = rsqrtf(fmaxf(var,0.f) + 1e-5f);
        #pragma unroll
        for (int m=0;m<8;m++){
            int dd = lane*8+m;
            hs[tok*68+dd] = (v[m]-mean)*rstd*__ldg(gam+dd) + __ldg(bet+dd);
        }
    }
    __syncthreads();

    // ---- GEMM1: 32 lanes x 16 rowgroups, 4 tokens x 2 adj cols ----
    int c2 = tid & 31, rg = tid >> 5;
    float acc[4][2];
    #pragma unroll
    for (int r=0;r<4;r++){ acc[r][0]=0.f; acc[r][1]=0.f; }
    #pragma unroll 4
    for (int d=0; d<64; d+=4){
        float hv[4][4];
        #pragma unroll
        for (int r=0;r<4;r++){
            float4 u = *(const float4*)(hs + (rg*4+r)*68 + d);
            hv[r][0]=u.x; hv[r][1]=u.y; hv[r][2]=u.z; hv[r][3]=u.w;
        }
        #pragma unroll
        for (int dd=0; dd<4; dd++){
            float2 w01 = *(const float2*)(W1s + (d+dd)*66 + 2*c2);
            #pragma unroll
            for (int r=0;r<4;r++){
                acc[r][0] += hv[r][dd]*w01.x;
                acc[r][1] += hv[r][dd]*w01.y;
            }
        }
    }
    __syncthreads();
    #pragma unroll
    for (int r=0;r<4;r++)
        #pragma unroll
        for (int e=0;e<2;e++){
            float z = acc[r][e] + bs[2*c2 + e];
            hs[(rg*4+r)*68 + 2*c2 + e] = 0.5f*z*(1.f + erff(z*0.7071067811865475f));
        }
    __syncthreads();

    // ---- GEMM2 + residual ----
    float acc2[4][2];
    #pragma unroll
    for (int r=0;r<4;r++){ acc2[r][0]=0.f; acc2[r][1]=0.f; }
    #pragma unroll 4
    for (int d=0; d<64; d+=4){
        float hv[4][4];
        #pragma unroll
        for (int r=0;r<4;r++){
            float4 u = *(const float4*)(hs + (rg*4+r)*68 + d);
            hv[r][0]=u.x; hv[r][1]=u.y; hv[r][2]=u.z; hv[r][3]=u.w;
        }
        #pragma unroll
        for (int dd=0; dd<4; dd++){
            float2 w01 = *(const float2*)(W2s + (d+dd)*66 + 2*c2);
            #pragma unroll
            for (int r=0;r<4;r++){
                acc2[r][0] += hv[r][dd]*w01.x;
                acc2[r][1] += hv[r][dd]*w01.y;
            }
        }
    }
    int gt0 = blockIdx.x*64 + rg*4;
    #pragma unroll
    for (int r=0;r<4;r++){
        float2 val;
        val.x = xs[(rg*4+r)*68 + 2*c2]     + acc2[r][0] + bs[64 + 2*c2];
        val.y = xs[(rg*4+r)*68 + 2*c2 + 1] + acc2[r][1] + bs[64 + 2*c2 + 1];
        *(float2*)(g_x + ((size_t)(gt0+r))*64 + 2*c2) = val;
    }
}

// ============ 1x1 conv out + sigmoid ============
__global__ void k_out(const float* __restrict__ ow, const float* __restrict__ ob,
                      float* __restrict__ out){
    int id = blockIdx.x*256 + threadIdx.x;
    int t = id & (TT-1), b = id >> 12;
    const float4* xp = (const float4*)(g_x + (size_t)id*64);
    float a0 = __ldg(ob), a1 = __ldg(ob+1);
    #pragma unroll
    for (int d4=0; d4<16; d4++){
        float4 xv = xp[d4];
        a0 += xv.x*__ldg(ow+d4*4) + xv.y*__ldg(ow+d4*4+1) + xv.z*__ldg(ow+d4*4+2) + xv.w*__ldg(ow+d4*4+3);
        a1 += xv.x*__ldg(ow+64+d4*4) + xv.y*__ldg(ow+64+d4*4+1) + xv.z*__ldg(ow+64+d4*4+2) + xv.w*__ldg(ow+64+d4*4+3);
    }
    out[((size_t)(b*2))*TT + t]   = 1.f/(1.f+expf(-a0));
    out[((size_t)(b*2+1))*TT + t] = 1.f/(1.f+expf(-a1));
}

extern "C" void kernel_launch(void* const* d_in, const int* in_sizes, int n_in,
                              void* d_out, int out_size){
    const float* spec = (const float*)d_in[0];
    const float* c1w = (const float*)d_in[1];
    const float* c1b = (const float*)d_in[2];
    const float* c2w = (const float*)d_in[3];
    const float* c2b = (const float*)d_in[4];
    const float* c3w = (const float*)d_in[5];
    const float* c3b = (const float*)d_in[6];
    const float* Wq  = (const float*)d_in[7];
    const float* bq  = (const float*)d_in[8];
    const float* Wk  = (const float*)d_in[9];
    const float* bk  = (const float*)d_in[10];
    const float* Wv  = (const float*)d_in[11];
    const float* bv  = (const float*)d_in[12];
    const float* Er  = (const float*)d_in[13];
    const float* g1  = (const float*)d_in[14];
    const float* be1 = (const float*)d_in[15];
    const float* W1  = (const float*)d_in[16];
    const float* b1  = (const float*)d_in[17];
    const float* W2  = (const float*)d_in[18];
    const float* b2  = (const float*)d_in[19];
    const float* g2  = (const float*)d_in[20];
    const float* be2 = (const float*)d_in[21];
    const float* ow  = (const float*)d_in[22];
    const float* ob  = (const float*)d_in[23];

    cudaFuncSetAttribute(k_s2,  cudaFuncAttributeMaxDynamicSharedMemorySize, 65536);
    cudaFuncSetAttribute(k_s3,  cudaFuncAttributeMaxDynamicSharedMemorySize, 158208);
    cudaFuncSetAttribute(k_qkv, cudaFuncAttributeMaxDynamicSharedMemorySize, 67840);
    cudaFuncSetAttribute(k_attnff, cudaFuncAttributeMaxDynamicSharedMemorySize, 69120);

    k_s1<<<3328, 256>>>(spec, c1w, c1b);
    k_s2<<<dim3(64,8), 256, 65536>>>(c2w, c2b);
    k_s3<<<dim3(32,8), 512, 158208>>>(c3w, c3b);
    for (int L=0; L<11; L++){
        k_qkv<<<512, 512, 67840>>>(Wq+L*4096, bq+L*64, Wk+L*4096, bk+L*64,
                                   Wv+L*4096, bv+L*64, g1+L*64, be1+L*64);
        k_attnff<<<512, 512, 69120>>>(Er+L*384, 1<<L,
                                      W1+L*4096, b1+L*64, W2+L*4096, b2+L*64,
                                      g2+L*64, be2+L*64);
    }
    k_out<<<128, 256>>>(ow, ob, (float*)d_out);
}

// round 10
// speedup vs baseline: 1.2199x; 1.0173x over previous
#include <cuda_runtime.h>
#include <math.h>
#include <stdint.h>

#define TT 4096
#define NB 8
#define NBT (NB*TT)

__device__ __align__(256) float g_s1[NB*208*TT];
__device__ __align__(256) float g_s2[NB*160*TT];
__device__ __align__(256) float g_x [NBT*64];
__device__ __align__(256) float g_q [NBT*64];
__device__ __align__(256) float g_k [NBT*64];
__device__ __align__(256) float g_v [NBT*64];

__device__ __forceinline__ uint32_t f2tf32(float x){
    uint32_t r; asm("cvt.rna.tf32.f32 %0, %1;" : "=r"(r) : "f"(x)); return r;
}

#define MMA_TF32(d, a0,a1,a2,a3, b0,b1) \
  asm volatile("mma.sync.aligned.m16n8k8.row.col.f32.tf32.tf32.f32 " \
      "{%0,%1,%2,%3}, {%4,%5,%6,%7}, {%8,%9}, {%0,%1,%2,%3};" \
      : "+f"(d[0]), "+f"(d[1]), "+f"(d[2]), "+f"(d[3]) \
      : "r"(a0), "r"(a1), "r"(a2), "r"(a3), "r"(b0), "r"(b1))

// ============ stage 1: causal conv (1x3) + maxpool3(freq) + relu ============
__global__ void k_s1(const float* __restrict__ spec, const float* __restrict__ w,
                     const float* __restrict__ bias){
    int id = blockIdx.x*256 + threadIdx.x;
    int t  = id & (TT-1);
    int r  = id >> 12;
    int f2 = r % 26, b = r / 26;
    const float* sp = spec + (size_t)(b*81 + f2*3)*TT + t;
    float s[5][3];
    #pragma unroll
    for (int j=0;j<5;j++)
        #pragma unroll
        for (int i=0;i<3;i++)
            s[j][i] = (t+i < TT) ? sp[j*TT+i] : 0.f;
    #pragma unroll
    for (int c=0;c<8;c++){
        float a0=0.f,a1=0.f,a2=0.f;
        #pragma unroll
        for (int i=0;i<3;i++){
            if (t+i < TT){
                float w0=__ldg(w+(i*8+c)*3+0), w1=__ldg(w+(i*8+c)*3+1), w2=__ldg(w+(i*8+c)*3+2);
                float bb=__ldg(bias+i*8+c);
                a0 += bb + w0*s[0][i]+w1*s[1][i]+w2*s[2][i];
                a1 += bb + w0*s[1][i]+w1*s[2][i]+w2*s[3][i];
                a2 += bb + w0*s[2][i]+w1*s[3][i]+w2*s[4][i];
            }
        }
        float m = fmaxf(fmaxf(a0,a1),a2);
        g_s1[((size_t)(b*8+c)*26+f2)*TT + t] = fmaxf(m, 0.f);
    }
}

// ============ stage 2: conv (1x12) + maxpool3 + relu ============
__global__ void k_s2(const float* __restrict__ w2, const float* __restrict__ b2){
    extern __shared__ float sm[];
    float* s1s = sm;            // [208][64]
    float* ws  = sm + 208*64;   // 3072
    int tid = threadIdx.x, b = blockIdx.y, t0 = blockIdx.x*64;
    for (int i=tid; i<208*64; i+=256){
        int tl = i & 63, fr = i >> 6;
        s1s[i] = g_s1[((size_t)(b*208+fr))*TT + t0 + tl];
    }
    for (int i=tid; i<3072; i+=256) ws[i] = w2[i];
    __syncthreads();
    int tl = tid & 63, g = tid >> 6;
    for (int cb=0; cb<2; cb++){
        int co0 = g*8 + cb*4;
        float acc[4][5][3];
        #pragma unroll
        for (int u=0;u<4;u++){
            float bb = __ldg(b2 + co0 + u);
            #pragma unroll
            for (int f2=0;f2<5;f2++){ acc[u][f2][0]=bb; acc[u][f2][1]=bb; acc[u][f2][2]=bb; }
        }
        for (int cin=0; cin<8; cin++){
            float sv[26];
            #pragma unroll
            for (int ff=0; ff<26; ff++) sv[ff] = s1s[(cin*26+ff)*64 + tl];
            float w[4][12];
            #pragma unroll
            for (int u=0;u<4;u++)
                #pragma unroll
                for (int k=0;k<12;k++) w[u][k] = ws[(co0+u)*96 + cin*12 + k];
            #pragma unroll
            for (int f2=0; f2<5; f2++)
                #pragma unroll
                for (int k=0;k<12;k++)
                    #pragma unroll
                    for (int u=0;u<4;u++){
                        float wk = w[u][k];
                        acc[u][f2][0] += wk*sv[f2*3+k+0];
                        acc[u][f2][1] += wk*sv[f2*3+k+1];
                        acc[u][f2][2] += wk*sv[f2*3+k+2];
                    }
        }
        #pragma unroll
        for (int u=0;u<4;u++)
            #pragma unroll
            for (int f2=0;f2<5;f2++){
                float m = fmaxf(fmaxf(acc[u][f2][0],acc[u][f2][1]),acc[u][f2][2]);
                g_s2[((size_t)((b*32+co0+u)*5+f2))*TT + t0 + tl] = fmaxf(m, 0.f);
            }
    }
}

// ============ stage 3: causal conv (1x3, cin32,co64) + maxpool3 + relu ============
__global__ void __launch_bounds__(512) k_s3(const float* __restrict__ w3, const float* __restrict__ b3){
    extern __shared__ float sm[];
    float* s2s = sm;              // [160][132]
    float* w3s = sm + 160*132;    // 18432
    int tid = threadIdx.x, b = blockIdx.y, t0 = blockIdx.x*128;
    for (int i=tid; i<160*132; i+=512){
        int tl = i % 132, fr = i / 132;
        int tg = t0 + tl;
        s2s[i] = (tg < TT && tl < 130) ? g_s2[((size_t)(b*160+fr))*TT + tg] : 0.f;
    }
    for (int i=tid; i<18432; i+=512){
        int co = i & 63, r = i >> 6;
        int k = r % 3; r /= 3;
        int cin = r & 31, ii = r >> 5;
        w3s[i] = w3[((size_t)(ii*64+co)*32+cin)*3 + k];
    }
    __syncthreads();
    int co = tid & 63, tg8 = tid >> 6;
    float bb0 = __ldg(b3+co), bb1 = __ldg(b3+64+co), bb2 = __ldg(b3+128+co);
    for (int chunk=0; chunk<2; chunk++){
        int tlbase = tg8*16 + chunk*8;
        float acc[8][3];
        #pragma unroll
        for (int rr=0;rr<8;rr++){ acc[rr][0]=0.f; acc[rr][1]=0.f; acc[rr][2]=0.f; }
        for (int cin=0; cin<32; cin++){
            float sv[5][12];
            #pragma unroll
            for (int ff=0; ff<5; ff++){
                const float4* p = (const float4*)(s2s + (cin*5+ff)*132 + tlbase);
                float4 u0=p[0], u1=p[1], u2=p[2];
                sv[ff][0]=u0.x; sv[ff][1]=u0.y; sv[ff][2]=u0.z; sv[ff][3]=u0.w;
                sv[ff][4]=u1.x; sv[ff][5]=u1.y; sv[ff][6]=u1.z; sv[ff][7]=u1.w;
                sv[ff][8]=u2.x; sv[ff][9]=u2.y; sv[ff][10]=u2.z; sv[ff][11]=u2.w;
            }
            #pragma unroll
            for (int ii=0; ii<3; ii++)
                #pragma unroll
                for (int k=0; k<3; k++){
                    float wk = w3s[((ii*32+cin)*3+k)*64 + co];
                    #pragma unroll
                    for (int f=0; f<3; f++)
                        #pragma unroll
                        for (int rr=0; rr<8; rr++)
                            acc[rr][f] += wk*sv[f+k][rr+ii];
                }
        }
        #pragma unroll
        for (int rr=0; rr<8; rr++){
            int tg = t0 + tlbase + rr;
            float a0=acc[rr][0]+bb0, a1=acc[rr][1]+bb0, a2=acc[rr][2]+bb0;
            if (tg+1 < TT){ a0+=bb1; a1+=bb1; a2+=bb1; }
            if (tg+2 < TT){ a0+=bb2; a1+=bb2; a2+=bb2; }
            float m = fmaxf(fmaxf(a0,a1),a2);
            g_x[((size_t)(b*TT+tg))*64 + co] = fmaxf(m, 0.f);
        }
    }
}

// ============ LN1 + QKV via 3xTF32 mma (128 tokens/block, 512 thr) ============
// SMEM: Wh[64][200] Wl[64][200] (tf32 hi/lo of [Wq|Wk|Wv]^T), Hh[128][68], Hl[128][68], bs[192]
__global__ void __launch_bounds__(512) k_qkv(
        const float* __restrict__ Wq, const float* __restrict__ bq,
        const float* __restrict__ Wk, const float* __restrict__ bk,
        const float* __restrict__ Wv, const float* __restrict__ bv,
        const float* __restrict__ gam, const float* __restrict__ bet){
    extern __shared__ char smraw[];
    uint32_t* Wh = (uint32_t*)smraw;          // 12800
    uint32_t* Wl = Wh + 12800;                // 12800
    uint32_t* Hh = Wl + 12800;                // 8704
    uint32_t* Hl = Hh + 8704;                 // 8704
    float*    bs = (float*)(Hl + 8704);       // 192
    int tid = threadIdx.x;

    // stage weights, split hi/lo. B layout: [d][colglobal] pitch 200
    for (int i=tid; i<4096; i+=512){
        int col = i >> 6, d = i & 63;
        float wq = Wq[i], wk = Wk[i], wv = Wv[i];
        uint32_t h;
        h = f2tf32(wq); Wh[d*200+col]     = h; Wl[d*200+col]     = f2tf32(wq - __uint_as_float(h));
        h = f2tf32(wk); Wh[d*200+64+col]  = h; Wl[d*200+64+col]  = f2tf32(wk - __uint_as_float(h));
        h = f2tf32(wv); Wh[d*200+128+col] = h; Wl[d*200+128+col] = f2tf32(wv - __uint_as_float(h));
    }
    if (tid < 64){ bs[tid]=bq[tid]; bs[64+tid]=bk[tid]; bs[128+tid]=bv[tid]; }

    // LN1: 4 threads per token, 16 dims each; store tf32 hi/lo
    {
        int tok = tid >> 2, lane4 = tid & 3;
        int gtok = blockIdx.x*128 + tok;
        const float* xr = g_x + (size_t)gtok*64 + lane4*16;
        float v[16];
        #pragma unroll
        for (int c=0;c<4;c++){
            float4 u = *(const float4*)(xr + c*4);
            v[c*4]=u.x; v[c*4+1]=u.y; v[c*4+2]=u.z; v[c*4+3]=u.w;
        }
        float s=0.f, ss=0.f;
        #pragma unroll
        for (int m=0;m<16;m++){ s += v[m]; ss += v[m]*v[m]; }
        s += __shfl_xor_sync(0xffffffffu,s,1); ss += __shfl_xor_sync(0xffffffffu,ss,1);
        s += __shfl_xor_sync(0xffffffffu,s,2); ss += __shfl_xor_sync(0xffffffffu,ss,2);
        float mean = s*(1.f/64.f);
        float var  = ss*(1.f/64.f) - mean*mean;
        float rstd = rsqrtf(fmaxf(var,0.f) + 1e-5f);
        #pragma unroll
        for (int m=0;m<16;m++){
            int dd = lane4*16+m;
            float hv = (v[m]-mean)*rstd*__ldg(gam+dd) + __ldg(bet+dd);
            uint32_t hb = f2tf32(hv);
            Hh[tok*68+dd] = hb;
            Hl[tok*68+dd] = f2tf32(hv - __uint_as_float(hb));
        }
    }
    __syncthreads();

    // MMA: 16 warps = 8 m-tiles (16 tok) x 2 n-halves (96 cols)
    int lane = tid & 31, w = tid >> 5;
    int m0 = (w >> 1) << 4;
    int nbase = (w & 1) * 96;
    float acc[12][4];
    #pragma unroll
    for (int nt=0;nt<12;nt++){ acc[nt][0]=0.f; acc[nt][1]=0.f; acc[nt][2]=0.f; acc[nt][3]=0.f; }
    int arow = m0 + (lane>>2);
    #pragma unroll
    for (int kt=0; kt<8; kt++){
        int k0 = kt*8;
        int ai = arow*68 + k0 + (lane&3);
        uint32_t ah0=Hh[ai], ah1=Hh[ai+544], ah2=Hh[ai+4], ah3=Hh[ai+548];
        uint32_t al0=Hl[ai], al1=Hl[ai+544], al2=Hl[ai+4], al3=Hl[ai+548];
        int bi = (k0 + (lane&3))*200 + nbase + (lane>>2);
        #pragma unroll
        for (int nt=0; nt<12; nt++){
            uint32_t bh0=Wh[bi+nt*8], bh1=Wh[bi+nt*8+800];
            uint32_t bl0=Wl[bi+nt*8], bl1=Wl[bi+nt*8+800];
            MMA_TF32(acc[nt], al0,al1,al2,al3, bh0,bh1);
            MMA_TF32(acc[nt], ah0,ah1,ah2,ah3, bl0,bl1);
            MMA_TF32(acc[nt], ah0,ah1,ah2,ah3, bh0,bh1);
        }
    }
    // store: D[row=m0+(lane>>2) (+8)][col = nbase + nt*8 + 2*(lane&3) (+1)]
    int gt = blockIdx.x*128 + m0 + (lane>>2);
    #pragma unroll
    for (int nt=0; nt<12; nt++){
        int colg = nbase + nt*8 + 2*(lane&3);
        int seg = colg >> 6, cl = colg & 63;
        float* dst = (seg==0) ? g_q : (seg==1) ? g_k : g_v;
        float b0 = bs[colg], b1 = bs[colg+1];
        float2 v0; v0.x = acc[nt][0] + b0; v0.y = acc[nt][1] + b1;
        *(float2*)(dst + (size_t)gt*64 + cl) = v0;
        float2 v1; v1.x = acc[nt][2] + b0; v1.y = acc[nt][3] + b1;
        *(float2*)(dst + (size_t)(gt+8)*64 + cl) = v1;
    }
}

// ============ attention + residual + LN2 + FF + residual (fused, 512 thr) ============
__global__ void __launch_bounds__(512, 2) k_attnff(
        const float* __restrict__ Er, int shift,
        const float* __restrict__ W1p, const float* __restrict__ b1p,
        const float* __restrict__ W2p, const float* __restrict__ b2p,
        const float* __restrict__ gam, const float* __restrict__ bet){
    extern __shared__ float sm[];
    float* W1s = sm;            // [64][66]
    float* W2s = sm + 4224;     // [64][66]
    float* bs  = sm + 8448;     // 128
    float* xs  = sm + 8576;     // [64][68]
    float* hs  = sm + 12928;    // [64][68]
    int tid = threadIdx.x;
    for (int i=tid; i<4096; i+=512){
        int col = i >> 6, d = i & 63;
        W1s[d*66+col] = W1p[i];
        W2s[d*66+col] = W2p[i];
    }
    if (tid < 64){ bs[tid]=b1p[tid]; bs[64+tid]=b2p[tid]; }

    // ---- attention: 8 threads/token, 1 head each ----
    {
        int tok = tid >> 3, h = tid & 7;
        int gtok = blockIdx.x*64 + tok;
        int b = gtok >> 12, t = gtok & (TT-1);
        size_t bt = (size_t)b*TT + t;
        int sh[6]; sh[0]=0; sh[1]=0; sh[2]=shift; sh[3]=2*shift; sh[4]=3*shift; sh[5]=4*shift;
        const float* qp = g_q + bt*64 + h*8;
        float4 q0 = *(const float4*)qp, q1 = *(const float4*)(qp+4);
        float q[8] = {q0.x,q0.y,q0.z,q0.w,q1.x,q1.y,q1.z,q1.w};
        const float* er = Er + h*48;
        float lg[6];
        #pragma unroll
        for (int j=0;j<6;j++){
            float qe = 0.f;
            #pragma unroll
            for (int d=0;d<8;d++) qe += q[d]*__ldg(er + d*6 + j);
            lg[j] = qe;
        }
        #pragma unroll
        for (int j=0;j<6;j++){
            int tp = t - sh[j];
            float qk = 0.f;
            if (tp >= 0){
                const float* kp = g_k + ((size_t)b*TT+tp)*64 + h*8;
                float4 k0 = *(const float4*)kp, k1 = *(const float4*)(kp+4);
                qk = q[0]*k0.x + q[1]*k0.y + q[2]*k0.z + q[3]*k0.w
                   + q[4]*k1.x + q[5]*k1.y + q[6]*k1.z + q[7]*k1.w;
            }
            lg[j] = (qk + lg[j]) * 0.3535533905932738f;
        }
        float mx = lg[0];
        #pragma unroll
        for (int j=1;j<6;j++) mx = fmaxf(mx, lg[j]);
        float e[6], se = 0.f;
        #pragma unroll
        for (int j=0;j<6;j++){ e[j] = expf(lg[j]-mx); se += e[j]; }
        float inv = 1.f/se;
        float o[8] = {0,0,0,0,0,0,0,0};
        #pragma unroll
        for (int j=0;j<6;j++){
            int tp = t - sh[j];
            if (tp >= 0){
                const float* vp = g_v + ((size_t)b*TT+tp)*64 + h*8;
                float4 v0 = *(const float4*)vp, v1 = *(const float4*)(vp+4);
                float a = e[j];
                o[0]+=a*v0.x; o[1]+=a*v0.y; o[2]+=a*v0.z; o[3]+=a*v0.w;
                o[4]+=a*v1.x; o[5]+=a*v1.y; o[6]+=a*v1.z; o[7]+=a*v1.w;
            }
        }
        const float* xp = g_x + (size_t)gtok*64 + h*8;
        float4 x0 = *(const float4*)xp, x1 = *(const float4*)(xp+4);
        float* xd = xs + tok*68 + h*8;
        xd[0]=x0.x+o[0]*inv; xd[1]=x0.y+o[1]*inv; xd[2]=x0.z+o[2]*inv; xd[3]=x0.w+o[3]*inv;
        xd[4]=x1.x+o[4]*inv; xd[5]=x1.y+o[5]*inv; xd[6]=x1.z+o[6]*inv; xd[7]=x1.w+o[7]*inv;
    }
    __syncthreads();

    // ---- LN2: 8 threads/token ----
    {
        int tok = tid >> 3, lane = tid & 7;
        float v[8];
        #pragma unroll
        for (int m=0;m<8;m++) v[m] = xs[tok*68 + lane*8 + m];
        float s=0.f, ss=0.f;
        #pragma unroll
        for (int m=0;m<8;m++){ s += v[m]; ss += v[m]*v[m]; }
        s += __shfl_xor_sync(0xffffffffu,s,1); ss += __shfl_xor_sync(0xffffffffu,ss,1);
        s += __shfl_xor_sync(0xffffffffu,s,2); ss += __shfl_xor_sync(0xffffffffu,ss,2);
        s += __shfl_xor_sync(0xffffffffu,s,4); ss += __shfl_xor_sync(0xffffffffu,ss,4);
        float mean = s*(1.f/64.f);
        float var  = ss*(1.f/64.f) - mean*mean;
        float rstd = rsqrtf(fmaxf(var,0.f) + 1e-5f);
        #pragma unroll
        for (int m=0;m<8;m++){
            int dd = lane*8+m;
            hs[tok*68+dd] = (v[m]-mean)*rstd*__ldg(gam+dd) + __ldg(bet+dd);
        }
    }
    __syncthreads();

    // ---- GEMM1: 32 lanes x 16 rowgroups, 4 tokens x 2 adj cols ----
    int c2 = tid & 31, rg = tid >> 5;
    float acc[4][2];
    #pragma unroll
    for (int r=0;r<4;r++){ acc[r][0]=0.f; acc[r][1]=0.f; }
    #pragma unroll 4
    for (int d=0; d<64; d+=4){
        float hv[4][4];
        #pragma unroll
        for (int r=0;r<4;r++){
            float4 u = *(const float4*)(hs + (rg*4+r)*68 + d);
            hv[r][0]=u.x; hv[r][1]=u.y; hv[r][2]=u.z; hv[r][3]=u.w;
        }
        #pragma unroll
        for (int dd=0; dd<4; dd++){
            float2 w01 = *(const float2*)(W1s + (d+dd)*66 + 2*c2);
            #pragma unroll
            for (int r=0;r<4;r++){
                acc[r][0] += hv[r][dd]*w01.x;
                acc[r][1] += hv[r][dd]*w01.y;
            }
        }
    }
    __syncthreads();
    #pragma unroll
    for (int r=0;r<4;r++)
        #pragma unroll
        for (int e=0;e<2;e++){
            float z = acc[r][e] + bs[2*c2 + e];
            hs[(rg*4+r)*68 + 2*c2 + e] = 0.5f*z*(1.f + erff(z*0.7071067811865475f));
        }
    __syncthreads();

    // ---- GEMM2 + residual ----
    float acc2[4][2];
    #pragma unroll
    for (int r=0;r<4;r++){ acc2[r][0]=0.f; acc2[r][1]=0.f; }
    #pragma unroll 4
    for (int d=0; d<64; d+=4){
        float hv[4][4];
        #pragma unroll
        for (int r=0;r<4;r++){
            float4 u = *(const float4*)(hs + (rg*4+r)*68 + d);
            hv[r][0]=u.x; hv[r][1]=u.y; hv[r][2]=u.z; hv[r][3]=u.w;
        }
        #pragma unroll
        for (int dd=0; dd<4; dd++){
            float2 w01 = *(const float2*)(W2s + (d+dd)*66 + 2*c2);
            #pragma unroll
            for (int r=0;r<4;r++){
                acc2[r][0] += hv[r][dd]*w01.x;
                acc2[r][1] += hv[r][dd]*w01.y;
            }
        }
    }
    int gt0 = blockIdx.x*64 + rg*4;
    #pragma unroll
    for (int r=0;r<4;r++){
        float2 val;
        val.x = xs[(rg*4+r)*68 + 2*c2]     + acc2[r][0] + bs[64 + 2*c2];
        val.y = xs[(rg*4+r)*68 + 2*c2 + 1] + acc2[r][1] + bs[64 + 2*c2 + 1];
        *(float2*)(g_x + ((size_t)(gt0+r))*64 + 2*c2) = val;
    }
}

// ============ 1x1 conv out + sigmoid ============
__global__ void k_out(const float* __restrict__ ow, const float* __restrict__ ob,
                      float* __restrict__ out){
    int id = blockIdx.x*256 + threadIdx.x;
    int t = id & (TT-1), b = id >> 12;
    const float4* xp = (const float4*)(g_x + (size_t)id*64);
    float a0 = __ldg(ob), a1 = __ldg(ob+1);
    #pragma unroll
    for (int d4=0; d4<16; d4++){
        float4 xv = xp[d4];
        a0 += xv.x*__ldg(ow+d4*4) + xv.y*__ldg(ow+d4*4+1) + xv.z*__ldg(ow+d4*4+2) + xv.w*__ldg(ow+d4*4+3);
        a1 += xv.x*__ldg(ow+64+d4*4) + xv.y*__ldg(ow+64+d4*4+1) + xv.z*__ldg(ow+64+d4*4+2) + xv.w*__ldg(ow+64+d4*4+3);
    }
    out[((size_t)(b*2))*TT + t]   = 1.f/(1.f+expf(-a0));
    out[((size_t)(b*2+1))*TT + t] = 1.f/(1.f+expf(-a1));
}

extern "C" void kernel_launch(void* const* d_in, const int* in_sizes, int n_in,
                              void* d_out, int out_size){
    const float* spec = (const float*)d_in[0];
    const float* c1w = (const float*)d_in[1];
    const float* c1b = (const float*)d_in[2];
    const float* c2w = (const float*)d_in[3];
    const float* c2b = (const float*)d_in[4];
    const float* c3w = (const float*)d_in[5];
    const float* c3b = (const float*)d_in[6];
    const float* Wq  = (const float*)d_in[7];
    const float* bq  = (const float*)d_in[8];
    const float* Wk  = (const float*)d_in[9];
    const float* bk  = (const float*)d_in[10];
    const float* Wv  = (const float*)d_in[11];
    const float* bv  = (const float*)d_in[12];
    const float* Er  = (const float*)d_in[13];
    const float* g1  = (const float*)d_in[14];
    const float* be1 = (const float*)d_in[15];
    const float* W1  = (const float*)d_in[16];
    const float* b1  = (const float*)d_in[17];
    const float* W2  = (const float*)d_in[18];
    const float* b2  = (const float*)d_in[19];
    const float* g2  = (const float*)d_in[20];
    const float* be2 = (const float*)d_in[21];
    const float* ow  = (const float*)d_in[22];
    const float* ob  = (const float*)d_in[23];

    cudaFuncSetAttribute(k_s2,  cudaFuncAttributeMaxDynamicSharedMemorySize, 65536);
    cudaFuncSetAttribute(k_s3,  cudaFuncAttributeMaxDynamicSharedMemorySize, 158208);
    cudaFuncSetAttribute(k_qkv, cudaFuncAttributeMaxDynamicSharedMemorySize, 172800);
    cudaFuncSetAttribute(k_attnff, cudaFuncAttributeMaxDynamicSharedMemorySize, 69120);

    k_s1<<<3328, 256>>>(spec, c1w, c1b);
    k_s2<<<dim3(64,8), 256, 65536>>>(c2w, c2b);
    k_s3<<<dim3(32,8), 512, 158208>>>(c3w, c3b);
    for (int L=0; L<11; L++){
        k_qkv<<<256, 512, 172800>>>(Wq+L*4096, bq+L*64, Wk+L*4096, bk+L*64,
                                    Wv+L*4096, bv+L*64, g1+L*64, be1+L*64);
        k_attnff<<<512, 512, 69120>>>(Er+L*384, 1<<L,
                                      W1+L*4096, b1+L*64, W2+L*4096, b2+L*64,
                                      g2+L*64, be2+L*64);
    }
    k_out<<<128, 256>>>(ow, ob, (float*)d_out);
}